// round 12
// baseline (speedup 1.0000x reference)
#include <cuda_runtime.h>
#include <cuda_bf16.h>

#define NP     19000
#define E_SG   1500000
#define N_SG   800000
#define ND     1024
#define B_DD   4096
#define NB     148
#define NT     512
#define NWARP  16
#define CHUNK  129
#define AST2   264          // A tile row stride in bf16 elems (528B; %128=16 -> conflict-free)
#define WST2   264          // Ws row stride in bf16 elems
#define NTILE  297

// ---------------- persistent device state -----------------------------------
__device__ unsigned       g_xb  [NP * 128];   // dinv-prescaled x, bf16x2
__device__ unsigned       g_h1b [NP * 128];   // plain h1, bf16x2 (residual)
__device__ unsigned       g_h1sb[NP * 128];   // dinv-prescaled h1, bf16x2
__device__ unsigned       g_h2b [NP * 128];   // plain h2, bf16x2 (pool)
__device__ unsigned short g_w1t[256 * 256];   // W1^T bf16, n-major [n][k]
__device__ unsigned short g_w2t[256 * 256];
__device__ float          g_dinv[NP];
__device__ int            g_deg[NP];
__device__ int            g_rowstart[NP + 1];
__device__ int            g_fill[NP];
__device__ int            g_csr_src[E_SG];
__device__ float          g_drug[ND * 256];
__device__ int            g_drug_start[ND + 1];
__device__ int            g_part[NB];
__device__ int            g_poff[NB];
__device__ int            g_tctr[2];
__device__ unsigned       g_cnt;
__device__ unsigned       g_gen;

__device__ __forceinline__ unsigned pack2(float a, float b) {
    __nv_bfloat162 t = __floats2bfloat162_rn(a, b);
    return *(unsigned*)&t;
}
__device__ __forceinline__ float2 unpack2(unsigned u) {
    return __bfloat1622float2(*(__nv_bfloat162*)&u);
}
__device__ __forceinline__ unsigned short b16(float f) {
    __nv_bfloat16 h = __float2bfloat16_rn(f);
    return *(unsigned short*)&h;
}
__device__ __forceinline__ unsigned smem_u32(const void* p) {
    unsigned a;
    asm("{ .reg .u64 t; cvta.to.shared.u64 t, %1; cvt.u32.u64 %0, t; }"
        : "=r"(a) : "l"(p));
    return a;
}
__device__ __forceinline__ void ldsm_x4(unsigned& r0, unsigned& r1, unsigned& r2,
                                        unsigned& r3, unsigned addr) {
    asm volatile("ldmatrix.sync.aligned.m8n8.x4.shared.b16 {%0,%1,%2,%3}, [%4];"
                 : "=r"(r0), "=r"(r1), "=r"(r2), "=r"(r3) : "r"(addr));
}
__device__ __forceinline__ void mma_bf16(float* c, unsigned a0, unsigned a1,
                                         unsigned a2, unsigned a3,
                                         unsigned b0, unsigned b1) {
    asm volatile(
        "mma.sync.aligned.m16n8k16.row.col.f32.bf16.bf16.f32 "
        "{%0,%1,%2,%3}, {%4,%5,%6,%7}, {%8,%9}, {%0,%1,%2,%3};"
        : "+f"(c[0]), "+f"(c[1]), "+f"(c[2]), "+f"(c[3])
        : "r"(a0), "r"(a1), "r"(a2), "r"(a3), "r"(b0), "r"(b1));
}

// Software grid barrier; all 148 blocks co-resident (1 block/SM).
__device__ __forceinline__ void gridbar(unsigned gen0, unsigned k) {
    __syncthreads();
    if (threadIdx.x == 0) {
        __threadfence();
        unsigned pos = atomicAdd(&g_cnt, 1u);
        if (pos == NB - 1u) {
            atomicExch(&g_cnt, 0u);
            __threadfence();
            atomicAdd(&g_gen, 1u);
        } else {
            unsigned target = gen0 + k;
            while ((int)(*(volatile unsigned*)&g_gen - target) < 0) __nanosleep(64);
        }
        __threadfence();
    }
    __syncthreads();
}

// add one bf16 row (uint4 = 8 bf16) into a[8]
__device__ __forceinline__ void add_row(float* a, uint4 u) {
    float2 f;
    f = unpack2(u.x); a[0] += f.x; a[1] += f.y;
    f = unpack2(u.y); a[2] += f.x; a[3] += f.y;
    f = unpack2(u.z); a[4] += f.x; a[5] += f.y;
    f = unpack2(u.w); a[6] += f.x; a[7] += f.y;
}
// steer edge e into one of 4 row accumulators (warp-uniform branch)
__device__ __forceinline__ void acc4(float a[4][8], uint4 u, int e,
                                     int m1, int m2, int m3) {
    if (e < m1)      add_row(a[0], u);
    else if (e < m2) add_row(a[1], u);
    else if (e < m3) add_row(a[2], u);
    else             add_row(a[3], u);
}

// ---------------- fused GCN layer: 4-row streamed gather + HMMA GEMM --------
__device__ void layer_phase(const uint4* __restrict__ inb,       // prescaled bf16 rows
                            const unsigned short* __restrict__ Wt,
                            const float* __restrict__ bias,
                            const unsigned* __restrict__ resid,  // plain bf16 rows or null
                            unsigned* __restrict__ out_plain,
                            unsigned* __restrict__ out_scaled,
                            bool relu, int layer,
                            unsigned short* A_s, unsigned short* Ws, int* s_tile) {
    const int tid  = threadIdx.x;
    const int lane = tid & 31;
    const int wid  = tid >> 5;
    const unsigned baseA = smem_u32(A_s);
    const unsigned baseW = smem_u32(Ws);

    // ---- stage FULL W (256x256 bf16) into smem once per layer ----
    for (int i = tid; i < 8192; i += NT) {
        int n = i >> 5, o = i & 31;
        uint4 v = *(const uint4*)&Wt[n * 256 + o * 8];
        *(uint4*)&Ws[n * WST2 + o * 8] = v;
    }
    __syncthreads();

    for (;;) {
        __syncthreads();
        if (tid == 0) *s_tile = atomicAdd(&g_tctr[layer], 1);
        __syncthreads();
        const int tile = *s_tile;
        if (tile >= NTILE) break;
        const int r0 = tile * 64;

        // ---- gather: warp wid streams the combined edge range of its 4 rows
        {
            const int rw = r0 + wid * 4;
            const int c0 = min(rw,     NP), c1 = min(rw + 1, NP);
            const int c2 = min(rw + 2, NP), c3 = min(rw + 3, NP);
            const int c4 = min(rw + 4, NP);
            const int beg = g_rowstart[c0];
            const int m1  = g_rowstart[c1];
            const int m2  = g_rowstart[c2];
            const int m3  = g_rowstart[c3];
            const int end = g_rowstart[c4];

            float a[4][8];
            #pragma unroll
            for (int i = 0; i < 4; i++)
                #pragma unroll
                for (int j = 0; j < 8; j++) a[i][j] = 0.f;

            for (int base = beg; base < end; base += 32) {
                int m = min(32, end - base);
                int sidx = 0;
                if (lane < m) sidx = g_csr_src[base + lane] * 32;
                int k = 0;
                for (; k + 8 <= m; k += 8) {
                    int i0 = __shfl_sync(0xffffffffu, sidx, k);
                    int i1 = __shfl_sync(0xffffffffu, sidx, k + 1);
                    int i2 = __shfl_sync(0xffffffffu, sidx, k + 2);
                    int i3 = __shfl_sync(0xffffffffu, sidx, k + 3);
                    int i4 = __shfl_sync(0xffffffffu, sidx, k + 4);
                    int i5 = __shfl_sync(0xffffffffu, sidx, k + 5);
                    int i6 = __shfl_sync(0xffffffffu, sidx, k + 6);
                    int i7 = __shfl_sync(0xffffffffu, sidx, k + 7);
                    uint4 u0 = inb[i0 + lane];
                    uint4 u1 = inb[i1 + lane];
                    uint4 u2 = inb[i2 + lane];
                    uint4 u3 = inb[i3 + lane];
                    uint4 u4 = inb[i4 + lane];
                    uint4 u5 = inb[i5 + lane];
                    uint4 u6 = inb[i6 + lane];
                    uint4 u7 = inb[i7 + lane];
                    int e = base + k;
                    acc4(a, u0, e,     m1, m2, m3);
                    acc4(a, u1, e + 1, m1, m2, m3);
                    acc4(a, u2, e + 2, m1, m2, m3);
                    acc4(a, u3, e + 3, m1, m2, m3);
                    acc4(a, u4, e + 4, m1, m2, m3);
                    acc4(a, u5, e + 5, m1, m2, m3);
                    acc4(a, u6, e + 6, m1, m2, m3);
                    acc4(a, u7, e + 7, m1, m2, m3);
                }
                for (; k < m; k++) {
                    int i0 = __shfl_sync(0xffffffffu, sidx, k);
                    uint4 u0 = inb[i0 + lane];
                    acc4(a, u0, base + k, m1, m2, m3);
                }
            }
            // self terms + final dinv scale, store to A tile
            #pragma unroll
            for (int i = 0; i < 4; i++) {
                int r = rw + i;
                if (r < NP) {
                    uint4 us = inb[r * 32 + lane];
                    add_row(a[i], us);
                    float di = g_dinv[r];
                    #pragma unroll
                    for (int j = 0; j < 8; j++) a[i][j] *= di;
                }
                uint4 pA;
                pA.x = pack2(a[i][0], a[i][1]); pA.y = pack2(a[i][2], a[i][3]);
                pA.z = pack2(a[i][4], a[i][5]); pA.w = pack2(a[i][6], a[i][7]);
                *(uint4*)&A_s[(wid * 4 + i) * AST2 + lane * 8] = pA;
            }
        }
        __syncthreads();

        // ---- GEMM: H[64,256] = A_s(bf16) @ W(bf16) via mma.sync, W resident
        const int mg = wid & 3;
        const int ng = wid >> 2;
        const int g  = lane >> 3;
        float c[8][4];
        #pragma unroll
        for (int f = 0; f < 8; f++)
            #pragma unroll
            for (int q = 0; q < 4; q++) c[f][q] = 0.f;

        const int arow  = mg * 16 + (lane & 7) + (g & 1) * 8;
        const int akofs = (g >> 1) * 8;
        const unsigned aaddr0 = baseA + (unsigned)(arow * AST2 + akofs) * 2u;
        const int brow_base = ng * 64 + (lane & 7) + (g & 2) * 4;
        const int bkofs = (g & 1) * 8;

        #pragma unroll
        for (int kk = 0; kk < 256; kk += 16) {
            unsigned a0, a1, a2, a3;
            ldsm_x4(a0, a1, a2, a3, aaddr0 + (unsigned)kk * 2u);
            #pragma unroll
            for (int s = 0; s < 4; s++) {
                unsigned baddr = baseW +
                    (unsigned)((brow_base + s * 16) * WST2 + kk + bkofs) * 2u;
                unsigned b0, b1, b2, b3;
                ldsm_x4(b0, b1, b2, b3, baddr);
                mma_bf16(c[2 * s],     a0, a1, a2, a3, b0, b1);
                mma_bf16(c[2 * s + 1], a0, a1, a2, a3, b2, b3);
            }
        }

        // ---- epilogue: bias (+residual bf16) (+relu) -> plain / scaled bf16
        const int gr   = lane >> 2;
        const int colq = (lane & 3) * 2;
        #pragma unroll
        for (int f = 0; f < 8; f++) {
            int col = ng * 64 + f * 8 + colq;
            float2 bi = *(const float2*)&bias[col];
            #pragma unroll
            for (int half = 0; half < 2; half++) {
                int r = r0 + mg * 16 + gr + half * 8;
                if (r < NP) {
                    float vx = c[f][2 * half]     + bi.x;
                    float vy = c[f][2 * half + 1] + bi.y;
                    if (resid) {
                        float2 rr2 = unpack2(resid[r * 128 + (col >> 1)]);
                        vx += rr2.x; vy += rr2.y;
                    }
                    if (relu) { vx = fmaxf(vx, 0.f); vy = fmaxf(vy, 0.f); }
                    out_plain[r * 128 + (col >> 1)] = pack2(vx, vy);
                    if (out_scaled) {
                        float di = g_dinv[r];
                        out_scaled[r * 128 + (col >> 1)] = pack2(vx * di, vy * di);
                    }
                }
            }
        }
    }
}

// ---------------- the single mega-kernel ------------------------------------
__global__ __launch_bounds__(NT, 1) void mega_kernel(
    const float* __restrict__ x, const int* __restrict__ ddb,
    const int* __restrict__ src, const int* __restrict__ dst,
    const int* __restrict__ nodes, const int* __restrict__ avgix,
    const float* __restrict__ W1, const float* __restrict__ b1,
    const float* __restrict__ W2, const float* __restrict__ b2,
    float* __restrict__ out)
{
    extern __shared__ char smem_raw[];
    unsigned short* A_s = (unsigned short*)smem_raw;              // 33792B
    unsigned short* Ws  = (unsigned short*)(smem_raw + 33792);    // 135168B
    __shared__ unsigned s_gen0;
    __shared__ int s_tile;

    const int tid  = threadIdx.x;
    const int lane = tid & 31;
    const int wid  = tid >> 5;
    const int gtid = blockIdx.x * NT + tid;
    const int gs   = NB * NT;

    if (tid == 0) s_gen0 = *(volatile unsigned*)&g_gen;
    __syncthreads();
    const unsigned gen0 = s_gen0;

    // ---- P0: histogram + coalesced W->bf16^T + drug bounds + counters ----
    for (int e = gtid; e < E_SG; e += gs)
        atomicAdd(&g_deg[dst[e]], 1);
    if (blockIdx.x < 128) {
        const float* Win = (blockIdx.x < 64) ? W1 : W2;
        unsigned short* Wout = (blockIdx.x < 64) ? g_w1t : g_w2t;
        int tt = blockIdx.x & 63;
        int ty = tt >> 3;
        int tx = tt & 7;
        float* st = (float*)smem_raw;   // 32 x 33
        for (int idx = tid; idx < 1024; idx += NT) {
            int row = idx >> 5, colc = idx & 31;
            st[row * 33 + colc] = Win[(ty * 32 + row) * 256 + tx * 32 + colc];
        }
        __syncthreads();
        for (int idx = tid; idx < 1024; idx += NT) {
            int row = idx >> 5, colc = idx & 31;
            Wout[(tx * 32 + row) * 256 + ty * 32 + colc] = b16(st[colc * 33 + row]);
        }
    }
    if (gtid < 2) g_tctr[gtid] = 0;
    if (gtid <= ND) {
        if (gtid == ND) g_drug_start[ND] = N_SG;
        else {
            int lo = 0, hi = N_SG;
            while (lo < hi) {
                int mid = (lo + hi) >> 1;
                if (avgix[mid] < gtid) lo = mid + 1; else hi = mid;
            }
            g_drug_start[gtid] = lo;
        }
    }
    gridbar(gen0, 1);

    // ---- P1a: per-block chunk sums ----
    int* si = (int*)smem_raw;
    {
        int n0  = blockIdx.x * CHUNK;
        int len = NP - n0; if (len > CHUNK) len = CHUNK; if (len < 0) len = 0;
        int v = (tid < len) ? g_deg[n0 + tid] : 0;
        if (tid < CHUNK) si[tid] = v;
        __syncthreads();
        if (tid == 0) {
            int s = 0;
            for (int i = 0; i < len; i++) s += si[i];
            g_part[blockIdx.x] = s;
        }
    }
    gridbar(gen0, 2);

    // ---- P1b: block 0 scans the 148 partials ----
    if (blockIdx.x == 0) {
        int pv = (tid < NB) ? g_part[tid] : 0;
        if (tid < NB) si[tid] = pv;
        __syncthreads();
        if (tid == 0) {
            int run = 0;
            for (int i = 0; i < NB; i++) { int t = si[i]; si[i] = run; run += t; }
        }
        __syncthreads();
        if (tid < NB) g_poff[tid] = si[tid];
    }
    gridbar(gen0, 3);

    // ---- P1c: per-chunk prefix -> rowstart/fill/dinv ----
    {
        int n0  = blockIdx.x * CHUNK;
        int len = NP - n0; if (len > CHUNK) len = CHUNK; if (len < 0) len = 0;
        int v = (tid < len) ? g_deg[n0 + tid] : 0;
        if (tid < CHUNK) si[tid] = v;
        __syncthreads();
        if (tid == 0) {
            int run = g_poff[blockIdx.x];
            for (int i = 0; i < len; i++) { int t = si[i]; si[i] = run; run += t; }
        }
        __syncthreads();
        if (tid < len) {
            int node = n0 + tid;
            int rs = si[tid];
            g_rowstart[node] = rs;
            g_fill[node]     = rs;
            g_dinv[node]     = rsqrtf((float)v + 1.0f);
        }
        if (blockIdx.x == 0 && tid == 0) g_rowstart[NP] = E_SG;
    }
    gridbar(gen0, 4);

    // ---- P2: CSR fill + prescaled x->bf16 + reset g_deg ----
    for (int e = gtid; e < E_SG; e += gs) {
        int d   = dst[e];
        int pos = atomicAdd(&g_fill[d], 1);
        g_csr_src[pos] = src[e];
    }
    {
        const float2* x2 = (const float2*)x;
        for (int i = gtid; i < NP * 128; i += gs) {
            int r = i >> 7;
            float di = g_dinv[r];
            float2 v = x2[i];
            g_xb[i] = pack2(v.x * di, v.y * di);
        }
    }
    for (int i = gtid; i < NP; i += gs) g_deg[i] = 0;
    gridbar(gen0, 5);

    // ---- P3: layer 1 ----
    layer_phase((const uint4*)g_xb, g_w1t, b1, nullptr,
                g_h1b, g_h1sb, true, 0, A_s, Ws, &s_tile);
    gridbar(gen0, 6);

    // ---- P4: layer 2 ----
    layer_phase((const uint4*)g_h1sb, g_w2t, b2, g_h1b,
                g_h2b, nullptr, false, 1, A_s, Ws, &s_tile);
    gridbar(gen0, 7);

    // ---- P5: scatter-mean pooling from bf16 h2 (unroll-4) ----
    {
        const uint4* h2b = (const uint4*)g_h2b;
        float* P = (float*)smem_raw;
        for (int d = blockIdx.x; d < ND; d += NB) {
            int beg = g_drug_start[d];
            int end = g_drug_start[d + 1];
            float a[8] = {0.f, 0.f, 0.f, 0.f, 0.f, 0.f, 0.f, 0.f};
            for (int base = beg + wid * 32; base < end; base += NT) {
                int m = min(32, end - base);
                int nidx = 0;
                if (lane < m) nidx = nodes[base + lane] * 32;
                int k = 0;
                for (; k + 4 <= m; k += 4) {
                    int i0 = __shfl_sync(0xffffffffu, nidx, k);
                    int i1 = __shfl_sync(0xffffffffu, nidx, k + 1);
                    int i2 = __shfl_sync(0xffffffffu, nidx, k + 2);
                    int i3 = __shfl_sync(0xffffffffu, nidx, k + 3);
                    uint4 u0 = h2b[i0 + lane];
                    uint4 u1 = h2b[i1 + lane];
                    uint4 u2 = h2b[i2 + lane];
                    uint4 u3 = h2b[i3 + lane];
                    add_row(a, u0);
                    add_row(a, u1);
                    add_row(a, u2);
                    add_row(a, u3);
                }
                for (; k < m; k++) {
                    int i0 = __shfl_sync(0xffffffffu, nidx, k);
                    uint4 u0 = h2b[i0 + lane];
                    add_row(a, u0);
                }
            }
            __syncthreads();
            *(float4*)&P[wid * 256 + lane * 8]     = make_float4(a[0], a[1], a[2], a[3]);
            *(float4*)&P[wid * 256 + lane * 8 + 4] = make_float4(a[4], a[5], a[6], a[7]);
            __syncthreads();
            if (tid < 256) {
                float s = 0.f;
                #pragma unroll
                for (int w = 0; w < NWARP; w++) s += P[w * 256 + tid];
                float inv = 1.0f / fmaxf((float)(end - beg), 1.0f);
                g_drug[d * 256 + tid] = s * inv;
            }
            __syncthreads();
        }
    }
    gridbar(gen0, 8);

    // ---- P6: prediction head ----
    {
        const float4* gd = (const float4*)g_drug;
        for (int p = blockIdx.x * NWARP + wid; p < B_DD; p += NB * NWARP) {
            int a = ddb[p];
            int b = ddb[B_DD + p];
            float4 va0 = gd[a * 64 + lane], va1 = gd[a * 64 + 32 + lane];
            float4 vb0 = gd[b * 64 + lane], vb1 = gd[b * 64 + 32 + lane];
            float s = va0.x * vb0.x + va0.y * vb0.y + va0.z * vb0.z + va0.w * vb0.w
                    + va1.x * vb1.x + va1.y * vb1.y + va1.z * vb1.z + va1.w * vb1.w;
            #pragma unroll
            for (int off = 16; off; off >>= 1)
                s += __shfl_down_sync(0xffffffffu, s, off);
            if (lane == 0) out[p] = s;
        }
    }
}

// ---------------- launch ----------------------------------------------------
extern "C" void kernel_launch(void* const* d_in, const int* in_sizes, int n_in,
                              void* d_out, int out_size) {
    const float* x     = (const float*)d_in[0];
    const int*   ddb   = (const int*)d_in[1];
    const int*   sg_ei = (const int*)d_in[4];
    const int*   nodes = (const int*)d_in[5];
    const int*   avgix = (const int*)d_in[6];
    const float* W1    = (const float*)d_in[7];
    const float* b1    = (const float*)d_in[8];
    const float* W2    = (const float*)d_in[9];
    const float* b2    = (const float*)d_in[10];
    float* out = (float*)d_out;

    const int smem_bytes = 33792 + 135168;   // 168960
    static bool attr_set = false;
    if (!attr_set) {
        cudaFuncSetAttribute(mega_kernel, cudaFuncAttributeMaxDynamicSharedMemorySize,
                             smem_bytes);
        attr_set = true;
    }

    mega_kernel<<<NB, NT, smem_bytes>>>(x, ddb, sg_ei, sg_ei + E_SG,
                                        nodes, avgix, W1, b1, W2, b2, out);
}

// round 13
// speedup vs baseline: 1.1562x; 1.1562x over previous
#include <cuda_runtime.h>
#include <cuda_bf16.h>

#define NP     19000
#define E_SG   1500000
#define N_SG   800000
#define ND     1024
#define B_DD   4096
#define NB     148
#define NT     512
#define NWARP  16
#define CHUNK  129
#define AST2   264          // A tile row stride in bf16 elems (528B; %128=16 -> conflict-free)
#define WST2   264          // Ws row stride in bf16 elems
#define NTILE  297

// ---------------- persistent device state -----------------------------------
__device__ unsigned       g_xb  [NP * 128];   // dinv-prescaled x, bf16x2
__device__ unsigned       g_h1b [NP * 128];   // plain h1, bf16x2 (residual)
__device__ unsigned       g_h1sb[NP * 128];   // dinv-prescaled h1, bf16x2
__device__ unsigned       g_h2b [NP * 128];   // plain h2, bf16x2 (pool)
__device__ unsigned short g_w1t[256 * 256];   // W1^T bf16, n-major [n][k]
__device__ unsigned short g_w2t[256 * 256];
__device__ float          g_dinv[NP];
__device__ int            g_deg[NP];
__device__ int            g_rowstart[NP + 1];
__device__ int            g_fill[NP];
__device__ int            g_csr_src[E_SG];
__device__ float          g_drug[ND * 256];
__device__ int            g_drug_start[ND + 1];
__device__ int            g_part[NB];
__device__ int            g_poff[NB];
__device__ int            g_tctr[2];
__device__ unsigned       g_cnt;
__device__ unsigned       g_gen;

__device__ __forceinline__ unsigned pack2(float a, float b) {
    __nv_bfloat162 t = __floats2bfloat162_rn(a, b);
    return *(unsigned*)&t;
}
__device__ __forceinline__ float2 unpack2(unsigned u) {
    return __bfloat1622float2(*(__nv_bfloat162*)&u);
}
__device__ __forceinline__ unsigned short b16(float f) {
    __nv_bfloat16 h = __float2bfloat16_rn(f);
    return *(unsigned short*)&h;
}
__device__ __forceinline__ unsigned smem_u32(const void* p) {
    unsigned a;
    asm("{ .reg .u64 t; cvta.to.shared.u64 t, %1; cvt.u32.u64 %0, t; }"
        : "=r"(a) : "l"(p));
    return a;
}
__device__ __forceinline__ void ldsm_x4(unsigned& r0, unsigned& r1, unsigned& r2,
                                        unsigned& r3, unsigned addr) {
    asm volatile("ldmatrix.sync.aligned.m8n8.x4.shared.b16 {%0,%1,%2,%3}, [%4];"
                 : "=r"(r0), "=r"(r1), "=r"(r2), "=r"(r3) : "r"(addr));
}
__device__ __forceinline__ void mma_bf16(float* c, unsigned a0, unsigned a1,
                                         unsigned a2, unsigned a3,
                                         unsigned b0, unsigned b1) {
    asm volatile(
        "mma.sync.aligned.m16n8k16.row.col.f32.bf16.bf16.f32 "
        "{%0,%1,%2,%3}, {%4,%5,%6,%7}, {%8,%9}, {%0,%1,%2,%3};"
        : "+f"(c[0]), "+f"(c[1]), "+f"(c[2]), "+f"(c[3])
        : "r"(a0), "r"(a1), "r"(a2), "r"(a3), "r"(b0), "r"(b1));
}

// Software grid barrier; all 148 blocks co-resident (1 block/SM).
__device__ __forceinline__ void gridbar(unsigned gen0, unsigned k) {
    __syncthreads();
    if (threadIdx.x == 0) {
        __threadfence();
        unsigned pos = atomicAdd(&g_cnt, 1u);
        if (pos == NB - 1u) {
            atomicExch(&g_cnt, 0u);
            __threadfence();
            atomicAdd(&g_gen, 1u);
        } else {
            unsigned target = gen0 + k;
            while ((int)(*(volatile unsigned*)&g_gen - target) < 0) __nanosleep(64);
        }
        __threadfence();
    }
    __syncthreads();
}

// add one bf16 row (uint4 = 8 bf16) into a[8]
__device__ __forceinline__ void add_row(float* a, uint4 u) {
    float2 f;
    f = unpack2(u.x); a[0] += f.x; a[1] += f.y;
    f = unpack2(u.y); a[2] += f.x; a[3] += f.y;
    f = unpack2(u.z); a[4] += f.x; a[5] += f.y;
    f = unpack2(u.w); a[6] += f.x; a[7] += f.y;
}

// ---------------- fused GCN layer: prescaled-row-sum gather + HMMA GEMM -----
__device__ void layer_phase(const uint4* __restrict__ inb,       // prescaled bf16 rows
                            const unsigned short* __restrict__ Wt,
                            const float* __restrict__ bias,
                            const unsigned* __restrict__ resid,  // plain bf16 rows or null
                            unsigned* __restrict__ out_plain,
                            unsigned* __restrict__ out_scaled,
                            bool relu, int layer,
                            unsigned short* A_s, unsigned short* Ws, int* s_tile) {
    const int tid  = threadIdx.x;
    const int lane = tid & 31;
    const int wid  = tid >> 5;
    const unsigned baseA = smem_u32(A_s);
    const unsigned baseW = smem_u32(Ws);

    // ---- stage FULL W (256x256 bf16) into smem once per layer ----
    for (int i = tid; i < 8192; i += NT) {
        int n = i >> 5, o = i & 31;
        uint4 v = *(const uint4*)&Wt[n * 256 + o * 8];
        *(uint4*)&Ws[n * WST2 + o * 8] = v;
    }
    __syncthreads();

    for (;;) {
        __syncthreads();
        if (tid == 0) *s_tile = atomicAdd(&g_tctr[layer], 1);
        __syncthreads();
        const int tile = *s_tile;
        if (tile >= NTILE) break;
        const int r0 = tile * 64;

        // ---- gather: warp wid produces rows wid*4 .. wid*4+3 (cols lane*8..+7)
        for (int i = 0; i < 4; i++) {
            int rr = wid * 4 + i;
            int r  = r0 + rr;
            float a[8] = {0.f, 0.f, 0.f, 0.f, 0.f, 0.f, 0.f, 0.f};
            if (r < NP) {
                int beg = g_rowstart[r];
                int end = g_rowstart[r + 1];
                // software-pipelined chunk index staging
                int base = beg;
                int m    = min(32, end - base);
                int sidx = 0;
                if (base < end && lane < m) sidx = g_csr_src[base + lane] * 32;
                while (base < end) {
                    int nbase = base + 32;
                    int nm    = min(32, end - nbase);
                    int nsidx = 0;
                    if (nbase < end && lane < nm)
                        nsidx = g_csr_src[nbase + lane] * 32;  // prefetch next chunk
                    int k = 0;
                    for (; k + 4 <= m; k += 4) {
                        int i0 = __shfl_sync(0xffffffffu, sidx, k);
                        int i1 = __shfl_sync(0xffffffffu, sidx, k + 1);
                        int i2 = __shfl_sync(0xffffffffu, sidx, k + 2);
                        int i3 = __shfl_sync(0xffffffffu, sidx, k + 3);
                        uint4 u0 = inb[i0 + lane];
                        uint4 u1 = inb[i1 + lane];
                        uint4 u2 = inb[i2 + lane];
                        uint4 u3 = inb[i3 + lane];
                        add_row(a, u0);
                        add_row(a, u1);
                        add_row(a, u2);
                        add_row(a, u3);
                    }
                    for (; k < m; k++) {
                        int i0 = __shfl_sync(0xffffffffu, sidx, k);
                        uint4 u0 = inb[i0 + lane];
                        add_row(a, u0);
                    }
                    base = nbase; m = nm; sidx = nsidx;
                }
                // self term: prescaled self row, then one final *dinv_r
                uint4 us = inb[r * 32 + lane];
                add_row(a, us);
                float di = g_dinv[r];
                #pragma unroll
                for (int j = 0; j < 8; j++) a[j] *= di;
            }
            uint4 pA;
            pA.x = pack2(a[0], a[1]); pA.y = pack2(a[2], a[3]);
            pA.z = pack2(a[4], a[5]); pA.w = pack2(a[6], a[7]);
            *(uint4*)&A_s[rr * AST2 + lane * 8] = pA;
        }
        __syncthreads();

        // ---- GEMM: H[64,256] = A_s(bf16) @ W(bf16) via mma.sync, W resident
        const int mg = wid & 3;
        const int ng = wid >> 2;
        const int g  = lane >> 3;
        float c[8][4];
        #pragma unroll
        for (int f = 0; f < 8; f++)
            #pragma unroll
            for (int q = 0; q < 4; q++) c[f][q] = 0.f;

        const int arow  = mg * 16 + (lane & 7) + (g & 1) * 8;
        const int akofs = (g >> 1) * 8;
        const unsigned aaddr0 = baseA + (unsigned)(arow * AST2 + akofs) * 2u;
        const int brow_base = ng * 64 + (lane & 7) + (g & 2) * 4;
        const int bkofs = (g & 1) * 8;

        #pragma unroll
        for (int kk = 0; kk < 256; kk += 16) {
            unsigned a0, a1, a2, a3;
            ldsm_x4(a0, a1, a2, a3, aaddr0 + (unsigned)kk * 2u);
            #pragma unroll
            for (int s = 0; s < 4; s++) {
                unsigned baddr = baseW +
                    (unsigned)((brow_base + s * 16) * WST2 + kk + bkofs) * 2u;
                unsigned b0, b1, b2, b3;
                ldsm_x4(b0, b1, b2, b3, baddr);
                mma_bf16(c[2 * s],     a0, a1, a2, a3, b0, b1);
                mma_bf16(c[2 * s + 1], a0, a1, a2, a3, b2, b3);
            }
        }

        // ---- epilogue: bias (+residual bf16) (+relu) -> plain / scaled bf16
        const int gr   = lane >> 2;
        const int colq = (lane & 3) * 2;
        #pragma unroll
        for (int f = 0; f < 8; f++) {
            int col = ng * 64 + f * 8 + colq;
            float2 bi = *(const float2*)&bias[col];
            #pragma unroll
            for (int half = 0; half < 2; half++) {
                int r = r0 + mg * 16 + gr + half * 8;
                if (r < NP) {
                    float vx = c[f][2 * half]     + bi.x;
                    float vy = c[f][2 * half + 1] + bi.y;
                    if (resid) {
                        float2 rr2 = unpack2(resid[r * 128 + (col >> 1)]);
                        vx += rr2.x; vy += rr2.y;
                    }
                    if (relu) { vx = fmaxf(vx, 0.f); vy = fmaxf(vy, 0.f); }
                    out_plain[r * 128 + (col >> 1)] = pack2(vx, vy);
                    if (out_scaled) {
                        float di = g_dinv[r];
                        out_scaled[r * 128 + (col >> 1)] = pack2(vx * di, vy * di);
                    }
                }
            }
        }
    }
}

// ---------------- the single mega-kernel ------------------------------------
__global__ __launch_bounds__(NT, 1) void mega_kernel(
    const float* __restrict__ x, const int* __restrict__ ddb,
    const int* __restrict__ src, const int* __restrict__ dst,
    const int* __restrict__ nodes, const int* __restrict__ avgix,
    const float* __restrict__ W1, const float* __restrict__ b1,
    const float* __restrict__ W2, const float* __restrict__ b2,
    float* __restrict__ out)
{
    extern __shared__ char smem_raw[];
    unsigned short* A_s = (unsigned short*)smem_raw;              // 33792B
    unsigned short* Ws  = (unsigned short*)(smem_raw + 33792);    // 135168B
    __shared__ unsigned s_gen0;
    __shared__ int s_tile;

    const int tid  = threadIdx.x;
    const int lane = tid & 31;
    const int wid  = tid >> 5;
    const int gtid = blockIdx.x * NT + tid;
    const int gs   = NB * NT;

    if (tid == 0) s_gen0 = *(volatile unsigned*)&g_gen;
    __syncthreads();
    const unsigned gen0 = s_gen0;

    // ---- P0: histogram + coalesced W->bf16^T + drug bounds + counters ----
    for (int e = gtid; e < E_SG; e += gs)
        atomicAdd(&g_deg[dst[e]], 1);
    if (blockIdx.x < 128) {
        const float* Win = (blockIdx.x < 64) ? W1 : W2;
        unsigned short* Wout = (blockIdx.x < 64) ? g_w1t : g_w2t;
        int tt = blockIdx.x & 63;
        int ty = tt >> 3;
        int tx = tt & 7;
        float* st = (float*)smem_raw;   // 32 x 33
        for (int idx = tid; idx < 1024; idx += NT) {
            int row = idx >> 5, colc = idx & 31;
            st[row * 33 + colc] = Win[(ty * 32 + row) * 256 + tx * 32 + colc];
        }
        __syncthreads();
        for (int idx = tid; idx < 1024; idx += NT) {
            int row = idx >> 5, colc = idx & 31;
            Wout[(tx * 32 + row) * 256 + ty * 32 + colc] = b16(st[colc * 33 + row]);
        }
    }
    if (gtid < 2) g_tctr[gtid] = 0;
    if (gtid <= ND) {
        if (gtid == ND) g_drug_start[ND] = N_SG;
        else {
            int lo = 0, hi = N_SG;
            while (lo < hi) {
                int mid = (lo + hi) >> 1;
                if (avgix[mid] < gtid) lo = mid + 1; else hi = mid;
            }
            g_drug_start[gtid] = lo;
        }
    }
    gridbar(gen0, 1);

    // ---- P1a: per-block chunk sums ----
    int* si = (int*)smem_raw;
    {
        int n0  = blockIdx.x * CHUNK;
        int len = NP - n0; if (len > CHUNK) len = CHUNK; if (len < 0) len = 0;
        int v = (tid < len) ? g_deg[n0 + tid] : 0;
        if (tid < CHUNK) si[tid] = v;
        __syncthreads();
        if (tid == 0) {
            int s = 0;
            for (int i = 0; i < len; i++) s += si[i];
            g_part[blockIdx.x] = s;
        }
    }
    gridbar(gen0, 2);

    // ---- P1b: block 0 scans the 148 partials ----
    if (blockIdx.x == 0) {
        int pv = (tid < NB) ? g_part[tid] : 0;
        if (tid < NB) si[tid] = pv;
        __syncthreads();
        if (tid == 0) {
            int run = 0;
            for (int i = 0; i < NB; i++) { int t = si[i]; si[i] = run; run += t; }
        }
        __syncthreads();
        if (tid < NB) g_poff[tid] = si[tid];
    }
    gridbar(gen0, 3);

    // ---- P1c: per-chunk prefix -> rowstart/fill/dinv ----
    {
        int n0  = blockIdx.x * CHUNK;
        int len = NP - n0; if (len > CHUNK) len = CHUNK; if (len < 0) len = 0;
        int v = (tid < len) ? g_deg[n0 + tid] : 0;
        if (tid < CHUNK) si[tid] = v;
        __syncthreads();
        if (tid == 0) {
            int run = g_poff[blockIdx.x];
            for (int i = 0; i < len; i++) { int t = si[i]; si[i] = run; run += t; }
        }
        __syncthreads();
        if (tid < len) {
            int node = n0 + tid;
            int rs = si[tid];
            g_rowstart[node] = rs;
            g_fill[node]     = rs;
            g_dinv[node]     = rsqrtf((float)v + 1.0f);
        }
        if (blockIdx.x == 0 && tid == 0) g_rowstart[NP] = E_SG;
    }
    gridbar(gen0, 4);

    // ---- P2: CSR fill + prescaled x->bf16 + reset g_deg ----
    for (int e = gtid; e < E_SG; e += gs) {
        int d   = dst[e];
        int pos = atomicAdd(&g_fill[d], 1);
        g_csr_src[pos] = src[e];
    }
    {
        const float2* x2 = (const float2*)x;
        for (int i = gtid; i < NP * 128; i += gs) {
            int r = i >> 7;
            float di = g_dinv[r];
            float2 v = x2[i];
            g_xb[i] = pack2(v.x * di, v.y * di);
        }
    }
    for (int i = gtid; i < NP; i += gs) g_deg[i] = 0;
    gridbar(gen0, 5);

    // ---- P3: layer 1 ----
    layer_phase((const uint4*)g_xb, g_w1t, b1, nullptr,
                g_h1b, g_h1sb, true, 0, A_s, Ws, &s_tile);
    gridbar(gen0, 6);

    // ---- P4: layer 2 ----
    layer_phase((const uint4*)g_h1sb, g_w2t, b2, g_h1b,
                g_h2b, nullptr, false, 1, A_s, Ws, &s_tile);
    gridbar(gen0, 7);

    // ---- P5: scatter-mean pooling from bf16 h2 (pipelined staging) ----
    {
        const uint4* h2b = (const uint4*)g_h2b;
        float* P = (float*)smem_raw;
        for (int d = blockIdx.x; d < ND; d += NB) {
            int beg = g_drug_start[d];
            int end = g_drug_start[d + 1];
            float a[8] = {0.f, 0.f, 0.f, 0.f, 0.f, 0.f, 0.f, 0.f};
            int base = beg + wid * 32;
            int m    = min(32, end - base);
            int nidx = 0;
            if (base < end && lane < m) nidx = nodes[base + lane] * 32;
            while (base < end) {
                int nbase = base + NT;
                int nm    = min(32, end - nbase);
                int nnidx = 0;
                if (nbase < end && lane < nm)
                    nnidx = nodes[nbase + lane] * 32;   // prefetch next chunk
                int k = 0;
                for (; k + 4 <= m; k += 4) {
                    int i0 = __shfl_sync(0xffffffffu, nidx, k);
                    int i1 = __shfl_sync(0xffffffffu, nidx, k + 1);
                    int i2 = __shfl_sync(0xffffffffu, nidx, k + 2);
                    int i3 = __shfl_sync(0xffffffffu, nidx, k + 3);
                    uint4 u0 = h2b[i0 + lane];
                    uint4 u1 = h2b[i1 + lane];
                    uint4 u2 = h2b[i2 + lane];
                    uint4 u3 = h2b[i3 + lane];
                    add_row(a, u0);
                    add_row(a, u1);
                    add_row(a, u2);
                    add_row(a, u3);
                }
                for (; k < m; k++) {
                    int i0 = __shfl_sync(0xffffffffu, nidx, k);
                    uint4 u0 = h2b[i0 + lane];
                    add_row(a, u0);
                }
                base = nbase; m = nm; nidx = nnidx;
            }
            __syncthreads();
            *(float4*)&P[wid * 256 + lane * 8]     = make_float4(a[0], a[1], a[2], a[3]);
            *(float4*)&P[wid * 256 + lane * 8 + 4] = make_float4(a[4], a[5], a[6], a[7]);
            __syncthreads();
            if (tid < 256) {
                float s = 0.f;
                #pragma unroll
                for (int w = 0; w < NWARP; w++) s += P[w * 256 + tid];
                float inv = 1.0f / fmaxf((float)(end - beg), 1.0f);
                g_drug[d * 256 + tid] = s * inv;
            }
            __syncthreads();
        }
    }
    gridbar(gen0, 8);

    // ---- P6: prediction head ----
    {
        const float4* gd = (const float4*)g_drug;
        for (int p = blockIdx.x * NWARP + wid; p < B_DD; p += NB * NWARP) {
            int a = ddb[p];
            int b = ddb[B_DD + p];
            float4 va0 = gd[a * 64 + lane], va1 = gd[a * 64 + 32 + lane];
            float4 vb0 = gd[b * 64 + lane], vb1 = gd[b * 64 + 32 + lane];
            float s = va0.x * vb0.x + va0.y * vb0.y + va0.z * vb0.z + va0.w * vb0.w
                    + va1.x * vb1.x + va1.y * vb1.y + va1.z * vb1.z + va1.w * vb1.w;
            #pragma unroll
            for (int off = 16; off; off >>= 1)
                s += __shfl_down_sync(0xffffffffu, s, off);
            if (lane == 0) out[p] = s;
        }
    }
}

// ---------------- launch ----------------------------------------------------
extern "C" void kernel_launch(void* const* d_in, const int* in_sizes, int n_in,
                              void* d_out, int out_size) {
    const float* x     = (const float*)d_in[0];
    const int*   ddb   = (const int*)d_in[1];
    const int*   sg_ei = (const int*)d_in[4];
    const int*   nodes = (const int*)d_in[5];
    const int*   avgix = (const int*)d_in[6];
    const float* W1    = (const float*)d_in[7];
    const float* b1    = (const float*)d_in[8];
    const float* W2    = (const float*)d_in[9];
    const float* b2    = (const float*)d_in[10];
    float* out = (float*)d_out;

    const int smem_bytes = 33792 + 135168;   // 168960
    static bool attr_set = false;
    if (!attr_set) {
        cudaFuncSetAttribute(mega_kernel, cudaFuncAttributeMaxDynamicSharedMemorySize,
                             smem_bytes);
        attr_set = true;
    }

    mega_kernel<<<NB, NT, smem_bytes>>>(x, ddb, sg_ei, sg_ei + E_SG,
                                        nodes, avgix, W1, b1, W2, b2, out);
}

// round 14
// speedup vs baseline: 1.2635x; 1.0928x over previous
#include <cuda_runtime.h>
#include <cuda_bf16.h>

#define NP     19000
#define E_SG   1500000
#define N_SG   800000
#define ND     1024
#define B_DD   4096
#define NB     148
#define NT     512
#define NWARP  16
#define CHUNK  129
#define AST2   264          // A tile row stride in bf16 elems (528B; %128=16 -> conflict-free)
#define WST2   264          // Ws row stride in bf16 elems
#define NTILE  297

// ---------------- persistent device state -----------------------------------
__device__ unsigned       g_xb  [NP * 128];   // dinv-prescaled x, bf16x2
__device__ unsigned       g_h1b [NP * 128];   // plain h1, bf16x2 (residual)
__device__ unsigned       g_h1sb[NP * 128];   // dinv-prescaled h1, bf16x2
__device__ unsigned       g_h2b [NP * 128];   // plain h2, bf16x2 (pool)
__device__ unsigned short g_w1t[256 * 256];   // W1^T bf16, n-major [n][k]
__device__ unsigned short g_w2t[256 * 256];
__device__ float          g_dinv[NP];
__device__ int            g_deg[NP];
__device__ int            g_rowstart[NP + 1];
__device__ int            g_fill[NP];
__device__ int            g_csr_src[E_SG];
__device__ float          g_drug[ND * 256];
__device__ int            g_drug_start[ND + 1];
__device__ int            g_part[NB];
__device__ int            g_poff[NB];
__device__ int            g_tctr[2];
__device__ unsigned       g_cnt;
__device__ unsigned       g_gen;

__device__ __forceinline__ unsigned pack2(float a, float b) {
    __nv_bfloat162 t = __floats2bfloat162_rn(a, b);
    return *(unsigned*)&t;
}
__device__ __forceinline__ float2 unpack2(unsigned u) {
    return __bfloat1622float2(*(__nv_bfloat162*)&u);
}
__device__ __forceinline__ unsigned short b16(float f) {
    __nv_bfloat16 h = __float2bfloat16_rn(f);
    return *(unsigned short*)&h;
}
__device__ __forceinline__ unsigned badd2(unsigned a, unsigned b) {
    unsigned r;
    asm("add.rn.bf16x2 %0, %1, %2;" : "=r"(r) : "r"(a), "r"(b));
    return r;
}
__device__ __forceinline__ unsigned smem_u32(const void* p) {
    unsigned a;
    asm("{ .reg .u64 t; cvta.to.shared.u64 t, %1; cvt.u32.u64 %0, t; }"
        : "=r"(a) : "l"(p));
    return a;
}
__device__ __forceinline__ void ldsm_x4(unsigned& r0, unsigned& r1, unsigned& r2,
                                        unsigned& r3, unsigned addr) {
    asm volatile("ldmatrix.sync.aligned.m8n8.x4.shared.b16 {%0,%1,%2,%3}, [%4];"
                 : "=r"(r0), "=r"(r1), "=r"(r2), "=r"(r3) : "r"(addr));
}
__device__ __forceinline__ void mma_bf16(float* c, unsigned a0, unsigned a1,
                                         unsigned a2, unsigned a3,
                                         unsigned b0, unsigned b1) {
    asm volatile(
        "mma.sync.aligned.m16n8k16.row.col.f32.bf16.bf16.f32 "
        "{%0,%1,%2,%3}, {%4,%5,%6,%7}, {%8,%9}, {%0,%1,%2,%3};"
        : "+f"(c[0]), "+f"(c[1]), "+f"(c[2]), "+f"(c[3])
        : "r"(a0), "r"(a1), "r"(a2), "r"(a3), "r"(b0), "r"(b1));
}

// Software grid barrier; all 148 blocks co-resident (1 block/SM).
__device__ __forceinline__ void gridbar(unsigned gen0, unsigned k) {
    __syncthreads();
    if (threadIdx.x == 0) {
        __threadfence();
        unsigned pos = atomicAdd(&g_cnt, 1u);
        if (pos == NB - 1u) {
            atomicExch(&g_cnt, 0u);
            __threadfence();
            atomicAdd(&g_gen, 1u);
        } else {
            unsigned target = gen0 + k;
            while ((int)(*(volatile unsigned*)&g_gen - target) < 0) __nanosleep(64);
        }
        __threadfence();
    }
    __syncthreads();
}

// add one bf16 row (uint4 = 8 bf16) into a[8]
__device__ __forceinline__ void add_row(float* a, uint4 u) {
    float2 f;
    f = unpack2(u.x); a[0] += f.x; a[1] += f.y;
    f = unpack2(u.y); a[2] += f.x; a[3] += f.y;
    f = unpack2(u.z); a[4] += f.x; a[5] += f.y;
    f = unpack2(u.w); a[6] += f.x; a[7] += f.y;
}
// combine two bf16 rows pairwise (one bf16 rounding), return pair-sum
__device__ __forceinline__ uint4 pair_rows(uint4 u, uint4 v) {
    uint4 p;
    p.x = badd2(u.x, v.x); p.y = badd2(u.y, v.y);
    p.z = badd2(u.z, v.z); p.w = badd2(u.w, v.w);
    return p;
}

// ---------------- fused GCN layer: prescaled-row-sum gather + HMMA GEMM -----
__device__ void layer_phase(const uint4* __restrict__ inb,       // prescaled bf16 rows
                            const unsigned short* __restrict__ Wt,
                            const float* __restrict__ bias,
                            const unsigned* __restrict__ resid,  // plain bf16 rows or null
                            unsigned* __restrict__ out_plain,
                            unsigned* __restrict__ out_scaled,
                            bool relu, int layer,
                            unsigned short* A_s, unsigned short* Ws, int* s_tile) {
    const int tid  = threadIdx.x;
    const int lane = tid & 31;
    const int wid  = tid >> 5;
    const unsigned baseA = smem_u32(A_s);
    const unsigned baseW = smem_u32(Ws);

    // ---- stage FULL W (256x256 bf16) into smem once per layer ----
    for (int i = tid; i < 8192; i += NT) {
        int n = i >> 5, o = i & 31;
        uint4 v = *(const uint4*)&Wt[n * 256 + o * 8];
        *(uint4*)&Ws[n * WST2 + o * 8] = v;
    }
    __syncthreads();

    for (;;) {
        __syncthreads();
        if (tid == 0) *s_tile = atomicAdd(&g_tctr[layer], 1);
        __syncthreads();
        const int tile = *s_tile;
        if (tile >= NTILE) break;
        const int r0 = tile * 64;

        // ---- gather: warp wid produces rows wid*4 .. wid*4+3 (cols lane*8..+7)
        for (int i = 0; i < 4; i++) {
            int rr = wid * 4 + i;
            int r  = r0 + rr;
            float a[8] = {0.f, 0.f, 0.f, 0.f, 0.f, 0.f, 0.f, 0.f};
            if (r < NP) {
                int beg = g_rowstart[r];
                int end = g_rowstart[r + 1];
                // software-pipelined chunk index staging
                int base = beg;
                int m    = min(32, end - base);
                int sidx = 0;
                if (base < end && lane < m) sidx = g_csr_src[base + lane] * 32;
                while (base < end) {
                    int nbase = base + 32;
                    int nm    = min(32, end - nbase);
                    int nsidx = 0;
                    if (nbase < end && lane < nm)
                        nsidx = g_csr_src[nbase + lane] * 32;  // prefetch next chunk
                    int k = 0;
                    for (; k + 4 <= m; k += 4) {
                        int i0 = __shfl_sync(0xffffffffu, sidx, k);
                        int i1 = __shfl_sync(0xffffffffu, sidx, k + 1);
                        int i2 = __shfl_sync(0xffffffffu, sidx, k + 2);
                        int i3 = __shfl_sync(0xffffffffu, sidx, k + 3);
                        uint4 u0 = inb[i0 + lane];
                        uint4 u1 = inb[i1 + lane];
                        uint4 u2 = inb[i2 + lane];
                        uint4 u3 = inb[i3 + lane];
                        uint4 p = pair_rows(u0, u1);   // bf16 pairwise combine
                        uint4 q = pair_rows(u2, u3);
                        add_row(a, p);
                        add_row(a, q);
                    }
                    for (; k < m; k++) {
                        int i0 = __shfl_sync(0xffffffffu, sidx, k);
                        uint4 u0 = inb[i0 + lane];
                        add_row(a, u0);
                    }
                    base = nbase; m = nm; sidx = nsidx;
                }
                // self term: prescaled self row, then one final *dinv_r
                uint4 us = inb[r * 32 + lane];
                add_row(a, us);
                float di = g_dinv[r];
                #pragma unroll
                for (int j = 0; j < 8; j++) a[j] *= di;
            }
            uint4 pA;
            pA.x = pack2(a[0], a[1]); pA.y = pack2(a[2], a[3]);
            pA.z = pack2(a[4], a[5]); pA.w = pack2(a[6], a[7]);
            *(uint4*)&A_s[rr * AST2 + lane * 8] = pA;
        }
        __syncthreads();

        // ---- GEMM: H[64,256] = A_s(bf16) @ W(bf16) via mma.sync, W resident
        const int mg = wid & 3;
        const int ng = wid >> 2;
        const int g  = lane >> 3;
        float c[8][4];
        #pragma unroll
        for (int f = 0; f < 8; f++)
            #pragma unroll
            for (int q = 0; q < 4; q++) c[f][q] = 0.f;

        const int arow  = mg * 16 + (lane & 7) + (g & 1) * 8;
        const int akofs = (g >> 1) * 8;
        const unsigned aaddr0 = baseA + (unsigned)(arow * AST2 + akofs) * 2u;
        const int brow_base = ng * 64 + (lane & 7) + (g & 2) * 4;
        const int bkofs = (g & 1) * 8;

        #pragma unroll
        for (int kk = 0; kk < 256; kk += 16) {
            unsigned a0, a1, a2, a3;
            ldsm_x4(a0, a1, a2, a3, aaddr0 + (unsigned)kk * 2u);
            #pragma unroll
            for (int s = 0; s < 4; s++) {
                unsigned baddr = baseW +
                    (unsigned)((brow_base + s * 16) * WST2 + kk + bkofs) * 2u;
                unsigned b0, b1, b2, b3;
                ldsm_x4(b0, b1, b2, b3, baddr);
                mma_bf16(c[2 * s],     a0, a1, a2, a3, b0, b1);
                mma_bf16(c[2 * s + 1], a0, a1, a2, a3, b2, b3);
            }
        }

        // ---- epilogue: bias (+residual bf16) (+relu) -> plain / scaled bf16
        const int gr   = lane >> 2;
        const int colq = (lane & 3) * 2;
        #pragma unroll
        for (int f = 0; f < 8; f++) {
            int col = ng * 64 + f * 8 + colq;
            float2 bi = *(const float2*)&bias[col];
            #pragma unroll
            for (int half = 0; half < 2; half++) {
                int r = r0 + mg * 16 + gr + half * 8;
                if (r < NP) {
                    float vx = c[f][2 * half]     + bi.x;
                    float vy = c[f][2 * half + 1] + bi.y;
                    if (resid) {
                        float2 rr2 = unpack2(resid[r * 128 + (col >> 1)]);
                        vx += rr2.x; vy += rr2.y;
                    }
                    if (relu) { vx = fmaxf(vx, 0.f); vy = fmaxf(vy, 0.f); }
                    out_plain[r * 128 + (col >> 1)] = pack2(vx, vy);
                    if (out_scaled) {
                        float di = g_dinv[r];
                        out_scaled[r * 128 + (col >> 1)] = pack2(vx * di, vy * di);
                    }
                }
            }
        }
    }
}

// ---------------- the single mega-kernel ------------------------------------
__global__ __launch_bounds__(NT, 1) void mega_kernel(
    const float* __restrict__ x, const int* __restrict__ ddb,
    const int* __restrict__ src, const int* __restrict__ dst,
    const int* __restrict__ nodes, const int* __restrict__ avgix,
    const float* __restrict__ W1, const float* __restrict__ b1,
    const float* __restrict__ W2, const float* __restrict__ b2,
    float* __restrict__ out)
{
    extern __shared__ char smem_raw[];
    unsigned short* A_s = (unsigned short*)smem_raw;              // 33792B
    unsigned short* Ws  = (unsigned short*)(smem_raw + 33792);    // 135168B
    __shared__ unsigned s_gen0;
    __shared__ int s_tile;

    const int tid  = threadIdx.x;
    const int lane = tid & 31;
    const int wid  = tid >> 5;
    const int gtid = blockIdx.x * NT + tid;
    const int gs   = NB * NT;

    if (tid == 0) s_gen0 = *(volatile unsigned*)&g_gen;
    __syncthreads();
    const unsigned gen0 = s_gen0;

    // ---- P0: histogram + coalesced W->bf16^T + drug bounds + counters ----
    for (int e = gtid; e < E_SG; e += gs)
        atomicAdd(&g_deg[dst[e]], 1);
    if (blockIdx.x < 128) {
        const float* Win = (blockIdx.x < 64) ? W1 : W2;
        unsigned short* Wout = (blockIdx.x < 64) ? g_w1t : g_w2t;
        int tt = blockIdx.x & 63;
        int ty = tt >> 3;
        int tx = tt & 7;
        float* st = (float*)smem_raw;   // 32 x 33
        for (int idx = tid; idx < 1024; idx += NT) {
            int row = idx >> 5, colc = idx & 31;
            st[row * 33 + colc] = Win[(ty * 32 + row) * 256 + tx * 32 + colc];
        }
        __syncthreads();
        for (int idx = tid; idx < 1024; idx += NT) {
            int row = idx >> 5, colc = idx & 31;
            Wout[(tx * 32 + row) * 256 + ty * 32 + colc] = b16(st[colc * 33 + row]);
        }
    }
    if (gtid < 2) g_tctr[gtid] = 0;
    if (gtid <= ND) {
        if (gtid == ND) g_drug_start[ND] = N_SG;
        else {
            int lo = 0, hi = N_SG;
            while (lo < hi) {
                int mid = (lo + hi) >> 1;
                if (avgix[mid] < gtid) lo = mid + 1; else hi = mid;
            }
            g_drug_start[gtid] = lo;
        }
    }
    gridbar(gen0, 1);

    // ---- P1a: per-block chunk sums ----
    int* si = (int*)smem_raw;
    {
        int n0  = blockIdx.x * CHUNK;
        int len = NP - n0; if (len > CHUNK) len = CHUNK; if (len < 0) len = 0;
        int v = (tid < len) ? g_deg[n0 + tid] : 0;
        if (tid < CHUNK) si[tid] = v;
        __syncthreads();
        if (tid == 0) {
            int s = 0;
            for (int i = 0; i < len; i++) s += si[i];
            g_part[blockIdx.x] = s;
        }
    }
    gridbar(gen0, 2);

    // ---- P1b: block 0 scans the 148 partials ----
    if (blockIdx.x == 0) {
        int pv = (tid < NB) ? g_part[tid] : 0;
        if (tid < NB) si[tid] = pv;
        __syncthreads();
        if (tid == 0) {
            int run = 0;
            for (int i = 0; i < NB; i++) { int t = si[i]; si[i] = run; run += t; }
        }
        __syncthreads();
        if (tid < NB) g_poff[tid] = si[tid];
    }
    gridbar(gen0, 3);

    // ---- P1c: per-chunk prefix -> rowstart/fill/dinv ----
    {
        int n0  = blockIdx.x * CHUNK;
        int len = NP - n0; if (len > CHUNK) len = CHUNK; if (len < 0) len = 0;
        int v = (tid < len) ? g_deg[n0 + tid] : 0;
        if (tid < CHUNK) si[tid] = v;
        __syncthreads();
        if (tid == 0) {
            int run = g_poff[blockIdx.x];
            for (int i = 0; i < len; i++) { int t = si[i]; si[i] = run; run += t; }
        }
        __syncthreads();
        if (tid < len) {
            int node = n0 + tid;
            int rs = si[tid];
            g_rowstart[node] = rs;
            g_fill[node]     = rs;
            g_dinv[node]     = rsqrtf((float)v + 1.0f);
        }
        if (blockIdx.x == 0 && tid == 0) g_rowstart[NP] = E_SG;
    }
    gridbar(gen0, 4);

    // ---- P2: CSR fill + prescaled x->bf16 + reset g_deg ----
    for (int e = gtid; e < E_SG; e += gs) {
        int d   = dst[e];
        int pos = atomicAdd(&g_fill[d], 1);
        g_csr_src[pos] = src[e];
    }
    {
        const float2* x2 = (const float2*)x;
        for (int i = gtid; i < NP * 128; i += gs) {
            int r = i >> 7;
            float di = g_dinv[r];
            float2 v = x2[i];
            g_xb[i] = pack2(v.x * di, v.y * di);
        }
    }
    for (int i = gtid; i < NP; i += gs) g_deg[i] = 0;
    gridbar(gen0, 5);

    // ---- P3: layer 1 ----
    layer_phase((const uint4*)g_xb, g_w1t, b1, nullptr,
                g_h1b, g_h1sb, true, 0, A_s, Ws, &s_tile);
    gridbar(gen0, 6);

    // ---- P4: layer 2 ----
    layer_phase((const uint4*)g_h1sb, g_w2t, b2, g_h1b,
                g_h2b, nullptr, false, 1, A_s, Ws, &s_tile);
    gridbar(gen0, 7);

    // ---- P5: scatter-mean pooling from bf16 h2 (pipelined + pairwise) ----
    {
        const uint4* h2b = (const uint4*)g_h2b;
        float* P = (float*)smem_raw;
        for (int d = blockIdx.x; d < ND; d += NB) {
            int beg = g_drug_start[d];
            int end = g_drug_start[d + 1];
            float a[8] = {0.f, 0.f, 0.f, 0.f, 0.f, 0.f, 0.f, 0.f};
            int base = beg + wid * 32;
            int m    = min(32, end - base);
            int nidx = 0;
            if (base < end && lane < m) nidx = nodes[base + lane] * 32;
            while (base < end) {
                int nbase = base + NT;
                int nm    = min(32, end - nbase);
                int nnidx = 0;
                if (nbase < end && lane < nm)
                    nnidx = nodes[nbase + lane] * 32;   // prefetch next chunk
                int k = 0;
                for (; k + 4 <= m; k += 4) {
                    int i0 = __shfl_sync(0xffffffffu, nidx, k);
                    int i1 = __shfl_sync(0xffffffffu, nidx, k + 1);
                    int i2 = __shfl_sync(0xffffffffu, nidx, k + 2);
                    int i3 = __shfl_sync(0xffffffffu, nidx, k + 3);
                    uint4 u0 = h2b[i0 + lane];
                    uint4 u1 = h2b[i1 + lane];
                    uint4 u2 = h2b[i2 + lane];
                    uint4 u3 = h2b[i3 + lane];
                    uint4 p = pair_rows(u0, u1);
                    uint4 q = pair_rows(u2, u3);
                    add_row(a, p);
                    add_row(a, q);
                }
                for (; k < m; k++) {
                    int i0 = __shfl_sync(0xffffffffu, nidx, k);
                    uint4 u0 = h2b[i0 + lane];
                    add_row(a, u0);
                }
                base = nbase; m = nm; nidx = nnidx;
            }
            __syncthreads();
            *(float4*)&P[wid * 256 + lane * 8]     = make_float4(a[0], a[1], a[2], a[3]);
            *(float4*)&P[wid * 256 + lane * 8 + 4] = make_float4(a[4], a[5], a[6], a[7]);
            __syncthreads();
            if (tid < 256) {
                float s = 0.f;
                #pragma unroll
                for (int w = 0; w < NWARP; w++) s += P[w * 256 + tid];
                float inv = 1.0f / fmaxf((float)(end - beg), 1.0f);
                g_drug[d * 256 + tid] = s * inv;
            }
            __syncthreads();
        }
    }
    gridbar(gen0, 8);

    // ---- P6: prediction head ----
    {
        const float4* gd = (const float4*)g_drug;
        for (int p = blockIdx.x * NWARP + wid; p < B_DD; p += NB * NWARP) {
            int a = ddb[p];
            int b = ddb[B_DD + p];
            float4 va0 = gd[a * 64 + lane], va1 = gd[a * 64 + 32 + lane];
            float4 vb0 = gd[b * 64 + lane], vb1 = gd[b * 64 + 32 + lane];
            float s = va0.x * vb0.x + va0.y * vb0.y + va0.z * vb0.z + va0.w * vb0.w
                    + va1.x * vb1.x + va1.y * vb1.y + va1.z * vb1.z + va1.w * vb1.w;
            #pragma unroll
            for (int off = 16; off; off >>= 1)
                s += __shfl_down_sync(0xffffffffu, s, off);
            if (lane == 0) out[p] = s;
        }
    }
}

// ---------------- launch ----------------------------------------------------
extern "C" void kernel_launch(void* const* d_in, const int* in_sizes, int n_in,
                              void* d_out, int out_size) {
    const float* x     = (const float*)d_in[0];
    const int*   ddb   = (const int*)d_in[1];
    const int*   sg_ei = (const int*)d_in[4];
    const int*   nodes = (const int*)d_in[5];
    const int*   avgix = (const int*)d_in[6];
    const float* W1    = (const float*)d_in[7];
    const float* b1    = (const float*)d_in[8];
    const float* W2    = (const float*)d_in[9];
    const float* b2    = (const float*)d_in[10];
    float* out = (float*)d_out;

    const int smem_bytes = 33792 + 135168;   // 168960
    static bool attr_set = false;
    if (!attr_set) {
        cudaFuncSetAttribute(mega_kernel, cudaFuncAttributeMaxDynamicSharedMemorySize,
                             smem_bytes);
        attr_set = true;
    }

    mega_kernel<<<NB, NT, smem_bytes>>>(x, ddb, sg_ei, sg_ei + E_SG,
                                        nodes, avgix, W1, b1, W2, b2, out);
}

// round 15
// speedup vs baseline: 1.2827x; 1.0152x over previous
#include <cuda_runtime.h>
#include <cuda_bf16.h>

#define NP     19000
#define E_SG   1500000
#define N_SG   800000
#define ND     1024
#define B_DD   4096
#define NB     148
#define NT     512
#define NWARP  16
#define CHUNK  129
#define AST2   264          // A tile row stride in bf16 elems (528B; %128=16 -> conflict-free)
#define WST2   264          // Ws row stride in bf16 elems
#define NTILE  297

// ---------------- persistent device state -----------------------------------
__device__ unsigned       g_xb  [NP * 128];   // dinv-prescaled x, bf16x2
__device__ unsigned       g_h1b [NP * 128];   // plain h1, bf16x2 (residual)
__device__ unsigned       g_h1sb[NP * 128];   // dinv-prescaled h1, bf16x2
__device__ unsigned       g_h2b [NP * 128];   // plain h2, bf16x2 (pool)
__device__ unsigned short g_w1t[256 * 256];   // W1^T bf16, n-major [n][k]
__device__ unsigned short g_w2t[256 * 256];
__device__ float          g_dinv[NP];
__device__ int            g_deg[NP];
__device__ int            g_rowstart[NP + 1];
__device__ int            g_fill[NP];
__device__ int            g_csr_src[E_SG];
__device__ float          g_drug[ND * 256];
__device__ int            g_drug_start[ND + 1];
__device__ int            g_part[NB];
__device__ int            g_poff[NB];
__device__ int            g_tctr[2];
__device__ unsigned       g_cnt;
__device__ unsigned       g_gen;

__device__ __forceinline__ unsigned pack2(float a, float b) {
    __nv_bfloat162 t = __floats2bfloat162_rn(a, b);
    return *(unsigned*)&t;
}
__device__ __forceinline__ float2 unpack2(unsigned u) {
    return __bfloat1622float2(*(__nv_bfloat162*)&u);
}
__device__ __forceinline__ unsigned short b16(float f) {
    __nv_bfloat16 h = __float2bfloat16_rn(f);
    return *(unsigned short*)&h;
}
__device__ __forceinline__ unsigned badd2(unsigned a, unsigned b) {
    unsigned r;
    asm("add.rn.bf16x2 %0, %1, %2;" : "=r"(r) : "r"(a), "r"(b));
    return r;
}
__device__ __forceinline__ unsigned smem_u32(const void* p) {
    unsigned a;
    asm("{ .reg .u64 t; cvta.to.shared.u64 t, %1; cvt.u32.u64 %0, t; }"
        : "=r"(a) : "l"(p));
    return a;
}
__device__ __forceinline__ void ldsm_x4(unsigned& r0, unsigned& r1, unsigned& r2,
                                        unsigned& r3, unsigned addr) {
    asm volatile("ldmatrix.sync.aligned.m8n8.x4.shared.b16 {%0,%1,%2,%3}, [%4];"
                 : "=r"(r0), "=r"(r1), "=r"(r2), "=r"(r3) : "r"(addr));
}
__device__ __forceinline__ void mma_bf16(float* c, unsigned a0, unsigned a1,
                                         unsigned a2, unsigned a3,
                                         unsigned b0, unsigned b1) {
    asm volatile(
        "mma.sync.aligned.m16n8k16.row.col.f32.bf16.bf16.f32 "
        "{%0,%1,%2,%3}, {%4,%5,%6,%7}, {%8,%9}, {%0,%1,%2,%3};"
        : "+f"(c[0]), "+f"(c[1]), "+f"(c[2]), "+f"(c[3])
        : "r"(a0), "r"(a1), "r"(a2), "r"(a3), "r"(b0), "r"(b1));
}

// Software grid barrier; all 148 blocks co-resident (1 block/SM).
__device__ __forceinline__ void gridbar(unsigned gen0, unsigned k) {
    __syncthreads();
    if (threadIdx.x == 0) {
        __threadfence();
        unsigned pos = atomicAdd(&g_cnt, 1u);
        if (pos == NB - 1u) {
            atomicExch(&g_cnt, 0u);
            __threadfence();
            atomicAdd(&g_gen, 1u);
        } else {
            unsigned target = gen0 + k;
            while ((int)(*(volatile unsigned*)&g_gen - target) < 0) __nanosleep(64);
        }
        __threadfence();
    }
    __syncthreads();
}

// add one bf16 row (uint4 = 8 bf16) into a[8]
__device__ __forceinline__ void add_row(float* a, uint4 u) {
    float2 f;
    f = unpack2(u.x); a[0] += f.x; a[1] += f.y;
    f = unpack2(u.y); a[2] += f.x; a[3] += f.y;
    f = unpack2(u.z); a[4] += f.x; a[5] += f.y;
    f = unpack2(u.w); a[6] += f.x; a[7] += f.y;
}
// combine two bf16 rows pairwise (one bf16 rounding), return pair-sum
__device__ __forceinline__ uint4 pair_rows(uint4 u, uint4 v) {
    uint4 p;
    p.x = badd2(u.x, v.x); p.y = badd2(u.y, v.y);
    p.z = badd2(u.z, v.z); p.w = badd2(u.w, v.w);
    return p;
}

// ---------------- fused GCN layer: prescaled-row-sum gather + HMMA GEMM -----
__device__ void layer_phase(const uint4* __restrict__ inb,       // prescaled bf16 rows
                            const unsigned short* __restrict__ Wt,
                            const float* __restrict__ bias,
                            const unsigned* __restrict__ resid,  // plain bf16 rows or null
                            unsigned* __restrict__ out_plain,
                            unsigned* __restrict__ out_scaled,
                            bool relu, int layer,
                            unsigned short* A_s, unsigned short* Ws, int* s_tile) {
    const int tid  = threadIdx.x;
    const int lane = tid & 31;
    const int wid  = tid >> 5;
    const unsigned baseA = smem_u32(A_s);
    const unsigned baseW = smem_u32(Ws);

    // ---- stage FULL W (256x256 bf16) into smem once per layer ----
    for (int i = tid; i < 8192; i += NT) {
        int n = i >> 5, o = i & 31;
        uint4 v = *(const uint4*)&Wt[n * 256 + o * 8];
        *(uint4*)&Ws[n * WST2 + o * 8] = v;
    }
    __syncthreads();

    for (;;) {
        __syncthreads();
        if (tid == 0) *s_tile = atomicAdd(&g_tctr[layer], 1);
        __syncthreads();
        const int tile = *s_tile;
        if (tile >= NTILE) break;
        const int r0 = tile * 64;

        // ---- gather: warp wid produces rows wid*4 .. wid*4+3 (cols lane*8..+7)
        for (int i = 0; i < 4; i++) {
            int rr = wid * 4 + i;
            int r  = r0 + rr;
            float a[8] = {0.f, 0.f, 0.f, 0.f, 0.f, 0.f, 0.f, 0.f};
            if (r < NP) {
                int beg = g_rowstart[r];
                int end = g_rowstart[r + 1];
                // software-pipelined chunk index staging
                int base = beg;
                int m    = min(32, end - base);
                int sidx = 0;
                if (base < end && lane < m) sidx = g_csr_src[base + lane] * 32;
                while (base < end) {
                    int nbase = base + 32;
                    int nm    = min(32, end - nbase);
                    int nsidx = 0;
                    if (nbase < end && lane < nm)
                        nsidx = g_csr_src[nbase + lane] * 32;  // prefetch next chunk
                    int k = 0;
                    for (; k + 4 <= m; k += 4) {
                        int i0 = __shfl_sync(0xffffffffu, sidx, k);
                        int i1 = __shfl_sync(0xffffffffu, sidx, k + 1);
                        int i2 = __shfl_sync(0xffffffffu, sidx, k + 2);
                        int i3 = __shfl_sync(0xffffffffu, sidx, k + 3);
                        uint4 u0 = inb[i0 + lane];
                        uint4 u1 = inb[i1 + lane];
                        uint4 u2 = inb[i2 + lane];
                        uint4 u3 = inb[i3 + lane];
                        // depth-2 bf16 combine tree: 4 edges -> 1 row add
                        uint4 t = pair_rows(pair_rows(u0, u1), pair_rows(u2, u3));
                        add_row(a, t);
                    }
                    for (; k < m; k++) {
                        int i0 = __shfl_sync(0xffffffffu, sidx, k);
                        uint4 u0 = inb[i0 + lane];
                        add_row(a, u0);
                    }
                    base = nbase; m = nm; sidx = nsidx;
                }
                // self term: prescaled self row, then one final *dinv_r
                uint4 us = inb[r * 32 + lane];
                add_row(a, us);
                float di = g_dinv[r];
                #pragma unroll
                for (int j = 0; j < 8; j++) a[j] *= di;
            }
            uint4 pA;
            pA.x = pack2(a[0], a[1]); pA.y = pack2(a[2], a[3]);
            pA.z = pack2(a[4], a[5]); pA.w = pack2(a[6], a[7]);
            *(uint4*)&A_s[rr * AST2 + lane * 8] = pA;
        }
        __syncthreads();

        // ---- GEMM: H[64,256] = A_s(bf16) @ W(bf16) via mma.sync, W resident
        const int mg = wid & 3;
        const int ng = wid >> 2;
        const int g  = lane >> 3;
        float c[8][4];
        #pragma unroll
        for (int f = 0; f < 8; f++)
            #pragma unroll
            for (int q = 0; q < 4; q++) c[f][q] = 0.f;

        const int arow  = mg * 16 + (lane & 7) + (g & 1) * 8;
        const int akofs = (g >> 1) * 8;
        const unsigned aaddr0 = baseA + (unsigned)(arow * AST2 + akofs) * 2u;
        const int brow_base = ng * 64 + (lane & 7) + (g & 2) * 4;
        const int bkofs = (g & 1) * 8;

        #pragma unroll
        for (int kk = 0; kk < 256; kk += 16) {
            unsigned a0, a1, a2, a3;
            ldsm_x4(a0, a1, a2, a3, aaddr0 + (unsigned)kk * 2u);
            #pragma unroll
            for (int s = 0; s < 4; s++) {
                unsigned baddr = baseW +
                    (unsigned)((brow_base + s * 16) * WST2 + kk + bkofs) * 2u;
                unsigned b0, b1, b2, b3;
                ldsm_x4(b0, b1, b2, b3, baddr);
                mma_bf16(c[2 * s],     a0, a1, a2, a3, b0, b1);
                mma_bf16(c[2 * s + 1], a0, a1, a2, a3, b2, b3);
            }
        }

        // ---- epilogue: bias (+residual bf16) (+relu) -> plain / scaled bf16
        const int gr   = lane >> 2;
        const int colq = (lane & 3) * 2;
        #pragma unroll
        for (int f = 0; f < 8; f++) {
            int col = ng * 64 + f * 8 + colq;
            float2 bi = *(const float2*)&bias[col];
            #pragma unroll
            for (int half = 0; half < 2; half++) {
                int r = r0 + mg * 16 + gr + half * 8;
                if (r < NP) {
                    float vx = c[f][2 * half]     + bi.x;
                    float vy = c[f][2 * half + 1] + bi.y;
                    if (resid) {
                        float2 rr2 = unpack2(resid[r * 128 + (col >> 1)]);
                        vx += rr2.x; vy += rr2.y;
                    }
                    if (relu) { vx = fmaxf(vx, 0.f); vy = fmaxf(vy, 0.f); }
                    out_plain[r * 128 + (col >> 1)] = pack2(vx, vy);
                    if (out_scaled) {
                        float di = g_dinv[r];
                        out_scaled[r * 128 + (col >> 1)] = pack2(vx * di, vy * di);
                    }
                }
            }
        }
    }
}

// ---------------- the single mega-kernel ------------------------------------
__global__ __launch_bounds__(NT, 1) void mega_kernel(
    const float* __restrict__ x, const int* __restrict__ ddb,
    const int* __restrict__ src, const int* __restrict__ dst,
    const int* __restrict__ nodes, const int* __restrict__ avgix,
    const float* __restrict__ W1, const float* __restrict__ b1,
    const float* __restrict__ W2, const float* __restrict__ b2,
    float* __restrict__ out)
{
    extern __shared__ char smem_raw[];
    unsigned short* A_s = (unsigned short*)smem_raw;              // 33792B
    unsigned short* Ws  = (unsigned short*)(smem_raw + 33792);    // 135168B
    __shared__ unsigned s_gen0;
    __shared__ int s_tile;

    const int tid  = threadIdx.x;
    const int lane = tid & 31;
    const int wid  = tid >> 5;
    const int gtid = blockIdx.x * NT + tid;
    const int gs   = NB * NT;

    if (tid == 0) s_gen0 = *(volatile unsigned*)&g_gen;
    __syncthreads();
    const unsigned gen0 = s_gen0;

    // ---- P0: histogram + coalesced W->bf16^T + drug bounds + counters ----
    for (int e = gtid; e < E_SG; e += gs)
        atomicAdd(&g_deg[dst[e]], 1);
    if (blockIdx.x < 128) {
        const float* Win = (blockIdx.x < 64) ? W1 : W2;
        unsigned short* Wout = (blockIdx.x < 64) ? g_w1t : g_w2t;
        int tt = blockIdx.x & 63;
        int ty = tt >> 3;
        int tx = tt & 7;
        float* st = (float*)smem_raw;   // 32 x 33
        for (int idx = tid; idx < 1024; idx += NT) {
            int row = idx >> 5, colc = idx & 31;
            st[row * 33 + colc] = Win[(ty * 32 + row) * 256 + tx * 32 + colc];
        }
        __syncthreads();
        for (int idx = tid; idx < 1024; idx += NT) {
            int row = idx >> 5, colc = idx & 31;
            Wout[(tx * 32 + row) * 256 + ty * 32 + colc] = b16(st[colc * 33 + row]);
        }
    }
    if (gtid < 2) g_tctr[gtid] = 0;
    if (gtid <= ND) {
        if (gtid == ND) g_drug_start[ND] = N_SG;
        else {
            int lo = 0, hi = N_SG;
            while (lo < hi) {
                int mid = (lo + hi) >> 1;
                if (avgix[mid] < gtid) lo = mid + 1; else hi = mid;
            }
            g_drug_start[gtid] = lo;
        }
    }
    gridbar(gen0, 1);

    // ---- P1a: per-block chunk sums ----
    int* si = (int*)smem_raw;
    {
        int n0  = blockIdx.x * CHUNK;
        int len = NP - n0; if (len > CHUNK) len = CHUNK; if (len < 0) len = 0;
        int v = (tid < len) ? g_deg[n0 + tid] : 0;
        if (tid < CHUNK) si[tid] = v;
        __syncthreads();
        if (tid == 0) {
            int s = 0;
            for (int i = 0; i < len; i++) s += si[i];
            g_part[blockIdx.x] = s;
        }
    }
    gridbar(gen0, 2);

    // ---- P1b: block 0 scans the 148 partials ----
    if (blockIdx.x == 0) {
        int pv = (tid < NB) ? g_part[tid] : 0;
        if (tid < NB) si[tid] = pv;
        __syncthreads();
        if (tid == 0) {
            int run = 0;
            for (int i = 0; i < NB; i++) { int t = si[i]; si[i] = run; run += t; }
        }
        __syncthreads();
        if (tid < NB) g_poff[tid] = si[tid];
    }
    gridbar(gen0, 3);

    // ---- P1c: per-chunk prefix -> rowstart/fill/dinv ----
    {
        int n0  = blockIdx.x * CHUNK;
        int len = NP - n0; if (len > CHUNK) len = CHUNK; if (len < 0) len = 0;
        int v = (tid < len) ? g_deg[n0 + tid] : 0;
        if (tid < CHUNK) si[tid] = v;
        __syncthreads();
        if (tid == 0) {
            int run = g_poff[blockIdx.x];
            for (int i = 0; i < len; i++) { int t = si[i]; si[i] = run; run += t; }
        }
        __syncthreads();
        if (tid < len) {
            int node = n0 + tid;
            int rs = si[tid];
            g_rowstart[node] = rs;
            g_fill[node]     = rs;
            g_dinv[node]     = rsqrtf((float)v + 1.0f);
        }
        if (blockIdx.x == 0 && tid == 0) g_rowstart[NP] = E_SG;
    }
    gridbar(gen0, 4);

    // ---- P2: CSR fill + prescaled x->bf16 + reset g_deg ----
    for (int e = gtid; e < E_SG; e += gs) {
        int d   = dst[e];
        int pos = atomicAdd(&g_fill[d], 1);
        g_csr_src[pos] = src[e];
    }
    {
        const float2* x2 = (const float2*)x;
        for (int i = gtid; i < NP * 128; i += gs) {
            int r = i >> 7;
            float di = g_dinv[r];
            float2 v = x2[i];
            g_xb[i] = pack2(v.x * di, v.y * di);
        }
    }
    for (int i = gtid; i < NP; i += gs) g_deg[i] = 0;
    gridbar(gen0, 5);

    // ---- P3: layer 1 ----
    layer_phase((const uint4*)g_xb, g_w1t, b1, nullptr,
                g_h1b, g_h1sb, true, 0, A_s, Ws, &s_tile);
    gridbar(gen0, 6);

    // ---- P4: layer 2 ----
    layer_phase((const uint4*)g_h1sb, g_w2t, b2, g_h1b,
                g_h2b, nullptr, false, 1, A_s, Ws, &s_tile);
    gridbar(gen0, 7);

    // ---- P5: scatter-mean pooling from bf16 h2 (pipelined + depth-2 tree) ----
    {
        const uint4* h2b = (const uint4*)g_h2b;
        float* P = (float*)smem_raw;
        for (int d = blockIdx.x; d < ND; d += NB) {
            int beg = g_drug_start[d];
            int end = g_drug_start[d + 1];
            float a[8] = {0.f, 0.f, 0.f, 0.f, 0.f, 0.f, 0.f, 0.f};
            int base = beg + wid * 32;
            int m    = min(32, end - base);
            int nidx = 0;
            if (base < end && lane < m) nidx = nodes[base + lane] * 32;
            while (base < end) {
                int nbase = base + NT;
                int nm    = min(32, end - nbase);
                int nnidx = 0;
                if (nbase < end && lane < nm)
                    nnidx = nodes[nbase + lane] * 32;   // prefetch next chunk
                int k = 0;
                for (; k + 4 <= m; k += 4) {
                    int i0 = __shfl_sync(0xffffffffu, nidx, k);
                    int i1 = __shfl_sync(0xffffffffu, nidx, k + 1);
                    int i2 = __shfl_sync(0xffffffffu, nidx, k + 2);
                    int i3 = __shfl_sync(0xffffffffu, nidx, k + 3);
                    uint4 u0 = h2b[i0 + lane];
                    uint4 u1 = h2b[i1 + lane];
                    uint4 u2 = h2b[i2 + lane];
                    uint4 u3 = h2b[i3 + lane];
                    uint4 t = pair_rows(pair_rows(u0, u1), pair_rows(u2, u3));
                    add_row(a, t);
                }
                for (; k < m; k++) {
                    int i0 = __shfl_sync(0xffffffffu, nidx, k);
                    uint4 u0 = h2b[i0 + lane];
                    add_row(a, u0);
                }
                base = nbase; m = nm; nidx = nnidx;
            }
            __syncthreads();
            *(float4*)&P[wid * 256 + lane * 8]     = make_float4(a[0], a[1], a[2], a[3]);
            *(float4*)&P[wid * 256 + lane * 8 + 4] = make_float4(a[4], a[5], a[6], a[7]);
            __syncthreads();
            if (tid < 256) {
                float s = 0.f;
                #pragma unroll
                for (int w = 0; w < NWARP; w++) s += P[w * 256 + tid];
                float inv = 1.0f / fmaxf((float)(end - beg), 1.0f);
                g_drug[d * 256 + tid] = s * inv;
            }
            __syncthreads();
        }
    }
    gridbar(gen0, 8);

    // ---- P6: prediction head ----
    {
        const float4* gd = (const float4*)g_drug;
        for (int p = blockIdx.x * NWARP + wid; p < B_DD; p += NB * NWARP) {
            int a = ddb[p];
            int b = ddb[B_DD + p];
            float4 va0 = gd[a * 64 + lane], va1 = gd[a * 64 + 32 + lane];
            float4 vb0 = gd[b * 64 + lane], vb1 = gd[b * 64 + 32 + lane];
            float s = va0.x * vb0.x + va0.y * vb0.y + va0.z * vb0.z + va0.w * vb0.w
                    + va1.x * vb1.x + va1.y * vb1.y + va1.z * vb1.z + va1.w * vb1.w;
            #pragma unroll
            for (int off = 16; off; off >>= 1)
                s += __shfl_down_sync(0xffffffffu, s, off);
            if (lane == 0) out[p] = s;
        }
    }
}

// ---------------- launch ----------------------------------------------------
extern "C" void kernel_launch(void* const* d_in, const int* in_sizes, int n_in,
                              void* d_out, int out_size) {
    const float* x     = (const float*)d_in[0];
    const int*   ddb   = (const int*)d_in[1];
    const int*   sg_ei = (const int*)d_in[4];
    const int*   nodes = (const int*)d_in[5];
    const int*   avgix = (const int*)d_in[6];
    const float* W1    = (const float*)d_in[7];
    const float* b1    = (const float*)d_in[8];
    const float* W2    = (const float*)d_in[9];
    const float* b2    = (const float*)d_in[10];
    float* out = (float*)d_out;

    const int smem_bytes = 33792 + 135168;   // 168960
    static bool attr_set = false;
    if (!attr_set) {
        cudaFuncSetAttribute(mega_kernel, cudaFuncAttributeMaxDynamicSharedMemorySize,
                             smem_bytes);
        attr_set = true;
    }

    mega_kernel<<<NB, NT, smem_bytes>>>(x, ddb, sg_ei, sg_ei + E_SG,
                                        nodes, avgix, W1, b1, W2, b2, out);
}

// round 17
// speedup vs baseline: 1.4719x; 1.1475x over previous
#include <cuda_runtime.h>
#include <cuda_bf16.h>

#define NP     19000
#define E_SG   1500000
#define N_SG   800000
#define ND     1024
#define B_DD   4096
#define NB     148
#define NT     512
#define NWARP  16
#define CHUNK  129
#define AST2   264          // A tile row stride in bf16 elems (528B; %128=16 -> conflict-free)
#define WST2   264          // Ws row stride in bf16 elems
#define NTILE  297

// ---------------- persistent device state -----------------------------------
__device__ unsigned       g_xb  [NP * 128];   // dinv-prescaled x, bf16x2
__device__ unsigned       g_h1b [NP * 128];   // plain h1, bf16x2 (residual)
__device__ unsigned       g_h1sb[NP * 128];   // dinv-prescaled h1, bf16x2
__device__ unsigned       g_h2b [NP * 128];   // plain h2, bf16x2 (pool)
__device__ unsigned short g_w1t[256 * 256];   // W1^T bf16, n-major [n][k]
__device__ unsigned short g_w2t[256 * 256];
__device__ float          g_dinv[NP];
__device__ int            g_deg[NP];
__device__ int            g_rowstart[NP + 1];
__device__ int            g_fill[NP];
__device__ int            g_csr_src[E_SG];
__device__ float          g_drug[ND * 256];
__device__ int            g_drug_start[ND + 1];
__device__ int            g_part[NB];
__device__ int            g_poff[NB];
__device__ int            g_tctr[2];
__device__ unsigned       g_cnt;
__device__ unsigned       g_gen;

__device__ __forceinline__ unsigned pack2(float a, float b) {
    __nv_bfloat162 t = __floats2bfloat162_rn(a, b);
    return *(unsigned*)&t;
}
__device__ __forceinline__ float2 unpack2(unsigned u) {
    return __bfloat1622float2(*(__nv_bfloat162*)&u);
}
__device__ __forceinline__ unsigned short b16(float f) {
    __nv_bfloat16 h = __float2bfloat16_rn(f);
    return *(unsigned short*)&h;
}
__device__ __forceinline__ unsigned badd2(unsigned a, unsigned b) {
    unsigned r;
    asm("add.rn.bf16x2 %0, %1, %2;" : "=r"(r) : "r"(a), "r"(b));
    return r;
}
__device__ __forceinline__ unsigned smem_u32(const void* p) {
    unsigned a;
    asm("{ .reg .u64 t; cvta.to.shared.u64 t, %1; cvt.u32.u64 %0, t; }"
        : "=r"(a) : "l"(p));
    return a;
}
__device__ __forceinline__ void ldsm_x4(unsigned& r0, unsigned& r1, unsigned& r2,
                                        unsigned& r3, unsigned addr) {
    asm volatile("ldmatrix.sync.aligned.m8n8.x4.shared.b16 {%0,%1,%2,%3}, [%4];"
                 : "=r"(r0), "=r"(r1), "=r"(r2), "=r"(r3) : "r"(addr));
}
__device__ __forceinline__ void mma_bf16(float* c, unsigned a0, unsigned a1,
                                         unsigned a2, unsigned a3,
                                         unsigned b0, unsigned b1) {
    asm volatile(
        "mma.sync.aligned.m16n8k16.row.col.f32.bf16.bf16.f32 "
        "{%0,%1,%2,%3}, {%4,%5,%6,%7}, {%8,%9}, {%0,%1,%2,%3};"
        : "+f"(c[0]), "+f"(c[1]), "+f"(c[2]), "+f"(c[3])
        : "r"(a0), "r"(a1), "r"(a2), "r"(a3), "r"(b0), "r"(b1));
}

// Software grid barrier; all 148 blocks co-resident (1 block/SM).
__device__ __forceinline__ void gridbar(unsigned gen0, unsigned k) {
    __syncthreads();
    if (threadIdx.x == 0) {
        __threadfence();
        unsigned pos = atomicAdd(&g_cnt, 1u);
        if (pos == NB - 1u) {
            atomicExch(&g_cnt, 0u);
            __threadfence();
            atomicAdd(&g_gen, 1u);
        } else {
            unsigned target = gen0 + k;
            while ((int)(*(volatile unsigned*)&g_gen - target) < 0) __nanosleep(64);
        }
        __threadfence();
    }
    __syncthreads();
}

// add one bf16 row (uint4 = 8 bf16) into a[8]
__device__ __forceinline__ void add_row(float* a, uint4 u) {
    float2 f;
    f = unpack2(u.x); a[0] += f.x; a[1] += f.y;
    f = unpack2(u.y); a[2] += f.x; a[3] += f.y;
    f = unpack2(u.z); a[4] += f.x; a[5] += f.y;
    f = unpack2(u.w); a[6] += f.x; a[7] += f.y;
}
// combine two bf16 rows pairwise (one bf16 rounding), return pair-sum
__device__ __forceinline__ uint4 pair_rows(uint4 u, uint4 v) {
    uint4 p;
    p.x = badd2(u.x, v.x); p.y = badd2(u.y, v.y);
    p.z = badd2(u.z, v.z); p.w = badd2(u.w, v.w);
    return p;
}

// ---------------- fused GCN layer: prescaled-row-sum gather + HMMA GEMM -----
__device__ void layer_phase(const uint4* __restrict__ inb,       // prescaled bf16 rows
                            const unsigned short* __restrict__ Wt,
                            const float* __restrict__ bias,
                            const unsigned* __restrict__ resid,  // plain bf16 rows or null
                            unsigned* __restrict__ out_plain,
                            unsigned* __restrict__ out_scaled,
                            bool relu, int layer,
                            unsigned short* A_s, unsigned short* Ws, int* s_tile) {
    const int tid  = threadIdx.x;
    const int lane = tid & 31;
    const int wid  = tid >> 5;
    const unsigned baseA = smem_u32(A_s);
    const unsigned baseW = smem_u32(Ws);

    // ---- stage FULL W (256x256 bf16) into smem once per layer ----
    for (int i = tid; i < 8192; i += NT) {
        int n = i >> 5, o = i & 31;
        uint4 v = *(const uint4*)&Wt[n * 256 + o * 8];
        *(uint4*)&Ws[n * WST2 + o * 8] = v;
    }
    __syncthreads();

    for (;;) {
        __syncthreads();
        if (tid == 0) *s_tile = atomicAdd(&g_tctr[layer], 1);
        __syncthreads();
        const int tile = *s_tile;
        if (tile >= NTILE) break;
        const int r0 = tile * 64;

        // ---- gather: warp wid produces rows wid*4 .. wid*4+3 (cols lane*8..+7)
        for (int i = 0; i < 4; i++) {
            int rr = wid * 4 + i;
            int r  = r0 + rr;
            float a[8] = {0.f, 0.f, 0.f, 0.f, 0.f, 0.f, 0.f, 0.f};
            if (r < NP) {
                int beg = g_rowstart[r];
                int end = g_rowstart[r + 1];
                // software-pipelined chunk index staging
                int base = beg;
                int m    = min(32, end - base);
                int sidx = 0;
                if (base < end && lane < m) sidx = g_csr_src[base + lane] * 32;
                while (base < end) {
                    int nbase = base + 32;
                    int nm    = min(32, end - nbase);
                    int nsidx = 0;
                    if (nbase < end && lane < nm)
                        nsidx = g_csr_src[nbase + lane] * 32;  // prefetch next chunk
                    int k = 0;
                    for (; k + 8 <= m; k += 8) {
                        int i0 = __shfl_sync(0xffffffffu, sidx, k);
                        int i1 = __shfl_sync(0xffffffffu, sidx, k + 1);
                        int i2 = __shfl_sync(0xffffffffu, sidx, k + 2);
                        int i3 = __shfl_sync(0xffffffffu, sidx, k + 3);
                        int i4 = __shfl_sync(0xffffffffu, sidx, k + 4);
                        int i5 = __shfl_sync(0xffffffffu, sidx, k + 5);
                        int i6 = __shfl_sync(0xffffffffu, sidx, k + 6);
                        int i7 = __shfl_sync(0xffffffffu, sidx, k + 7);
                        uint4 u0 = inb[i0 + lane];
                        uint4 u1 = inb[i1 + lane];
                        uint4 u2 = inb[i2 + lane];
                        uint4 u3 = inb[i3 + lane];
                        uint4 u4 = inb[i4 + lane];
                        uint4 u5 = inb[i5 + lane];
                        uint4 u6 = inb[i6 + lane];
                        uint4 u7 = inb[i7 + lane];
                        // depth-3 bf16 combine tree: 8 edges -> 1 row add
                        uint4 t = pair_rows(
                            pair_rows(pair_rows(u0, u1), pair_rows(u2, u3)),
                            pair_rows(pair_rows(u4, u5), pair_rows(u6, u7)));
                        add_row(a, t);
                    }
                    for (; k + 4 <= m; k += 4) {
                        int i0 = __shfl_sync(0xffffffffu, sidx, k);
                        int i1 = __shfl_sync(0xffffffffu, sidx, k + 1);
                        int i2 = __shfl_sync(0xffffffffu, sidx, k + 2);
                        int i3 = __shfl_sync(0xffffffffu, sidx, k + 3);
                        uint4 u0 = inb[i0 + lane];
                        uint4 u1 = inb[i1 + lane];
                        uint4 u2 = inb[i2 + lane];
                        uint4 u3 = inb[i3 + lane];
                        uint4 t = pair_rows(pair_rows(u0, u1), pair_rows(u2, u3));
                        add_row(a, t);
                    }
                    for (; k < m; k++) {
                        int i0 = __shfl_sync(0xffffffffu, sidx, k);
                        uint4 u0 = inb[i0 + lane];
                        add_row(a, u0);
                    }
                    base = nbase; m = nm; sidx = nsidx;
                }
                // self term: prescaled self row, then one final *dinv_r
                uint4 us = inb[r * 32 + lane];
                add_row(a, us);
                float di = g_dinv[r];
                #pragma unroll
                for (int j = 0; j < 8; j++) a[j] *= di;
            }
            uint4 pA;
            pA.x = pack2(a[0], a[1]); pA.y = pack2(a[2], a[3]);
            pA.z = pack2(a[4], a[5]); pA.w = pack2(a[6], a[7]);
            *(uint4*)&A_s[rr * AST2 + lane * 8] = pA;
        }
        __syncthreads();

        // ---- GEMM: H[64,256] = A_s(bf16) @ W(bf16) via mma.sync, W resident
        const int mg = wid & 3;
        const int ng = wid >> 2;
        const int g  = lane >> 3;
        float c[8][4];
        #pragma unroll
        for (int f = 0; f < 8; f++)
            #pragma unroll
            for (int q = 0; q < 4; q++) c[f][q] = 0.f;

        const int arow  = mg * 16 + (lane & 7) + (g & 1) * 8;
        const int akofs = (g >> 1) * 8;
        const unsigned aaddr0 = baseA + (unsigned)(arow * AST2 + akofs) * 2u;
        const int brow_base = ng * 64 + (lane & 7) + (g & 2) * 4;
        const int bkofs = (g & 1) * 8;

        #pragma unroll
        for (int kk = 0; kk < 256; kk += 16) {
            unsigned a0, a1, a2, a3;
            ldsm_x4(a0, a1, a2, a3, aaddr0 + (unsigned)kk * 2u);
            #pragma unroll
            for (int s = 0; s < 4; s++) {
                unsigned baddr = baseW +
                    (unsigned)((brow_base + s * 16) * WST2 + kk + bkofs) * 2u;
                unsigned b0, b1, b2, b3;
                ldsm_x4(b0, b1, b2, b3, baddr);
                mma_bf16(c[2 * s],     a0, a1, a2, a3, b0, b1);
                mma_bf16(c[2 * s + 1], a0, a1, a2, a3, b2, b3);
            }
        }

        // ---- epilogue: bias (+residual bf16) (+relu) -> plain / scaled bf16
        const int gr   = lane >> 2;
        const int colq = (lane & 3) * 2;
        #pragma unroll
        for (int f = 0; f < 8; f++) {
            int col = ng * 64 + f * 8 + colq;
            float2 bi = *(const float2*)&bias[col];
            #pragma unroll
            for (int half = 0; half < 2; half++) {
                int r = r0 + mg * 16 + gr + half * 8;
                if (r < NP) {
                    float vx = c[f][2 * half]     + bi.x;
                    float vy = c[f][2 * half + 1] + bi.y;
                    if (resid) {
                        float2 rr2 = unpack2(resid[r * 128 + (col >> 1)]);
                        vx += rr2.x; vy += rr2.y;
                    }
                    if (relu) { vx = fmaxf(vx, 0.f); vy = fmaxf(vy, 0.f); }
                    out_plain[r * 128 + (col >> 1)] = pack2(vx, vy);
                    if (out_scaled) {
                        float di = g_dinv[r];
                        out_scaled[r * 128 + (col >> 1)] = pack2(vx * di, vy * di);
                    }
                }
            }
        }
    }
}

// ---------------- the single mega-kernel ------------------------------------
__global__ __launch_bounds__(NT, 1) void mega_kernel(
    const float* __restrict__ x, const int* __restrict__ ddb,
    const int* __restrict__ src, const int* __restrict__ dst,
    const int* __restrict__ nodes, const int* __restrict__ avgix,
    const float* __restrict__ W1, const float* __restrict__ b1,
    const float* __restrict__ W2, const float* __restrict__ b2,
    float* __restrict__ out)
{
    extern __shared__ char smem_raw[];
    unsigned short* A_s = (unsigned short*)smem_raw;              // 33792B
    unsigned short* Ws  = (unsigned short*)(smem_raw + 33792);    // 135168B
    __shared__ unsigned s_gen0;
    __shared__ int s_tile;

    const int tid  = threadIdx.x;
    const int lane = tid & 31;
    const int wid  = tid >> 5;
    const int gtid = blockIdx.x * NT + tid;
    const int gs   = NB * NT;

    if (tid == 0) s_gen0 = *(volatile unsigned*)&g_gen;
    __syncthreads();
    const unsigned gen0 = s_gen0;

    // ---- P0: histogram + coalesced W->bf16^T + drug bounds + counters ----
    for (int e = gtid; e < E_SG; e += gs)
        atomicAdd(&g_deg[dst[e]], 1);
    if (blockIdx.x < 128) {
        const float* Win = (blockIdx.x < 64) ? W1 : W2;
        unsigned short* Wout = (blockIdx.x < 64) ? g_w1t : g_w2t;
        int tt = blockIdx.x & 63;
        int ty = tt >> 3;
        int tx = tt & 7;
        float* st = (float*)smem_raw;   // 32 x 33
        for (int idx = tid; idx < 1024; idx += NT) {
            int row = idx >> 5, colc = idx & 31;
            st[row * 33 + colc] = Win[(ty * 32 + row) * 256 + tx * 32 + colc];
        }
        __syncthreads();
        for (int idx = tid; idx < 1024; idx += NT) {
            int row = idx >> 5, colc = idx & 31;
            Wout[(tx * 32 + row) * 256 + ty * 32 + colc] = b16(st[colc * 33 + row]);
        }
    }
    if (gtid < 2) g_tctr[gtid] = 0;
    if (gtid <= ND) {
        if (gtid == ND) g_drug_start[ND] = N_SG;
        else {
            int lo = 0, hi = N_SG;
            while (lo < hi) {
                int mid = (lo + hi) >> 1;
                if (avgix[mid] < gtid) lo = mid + 1; else hi = mid;
            }
            g_drug_start[gtid] = lo;
        }
    }
    gridbar(gen0, 1);

    // ---- P1a: per-block chunk sums ----
    int* si = (int*)smem_raw;
    {
        int n0  = blockIdx.x * CHUNK;
        int len = NP - n0; if (len > CHUNK) len = CHUNK; if (len < 0) len = 0;
        int v = (tid < len) ? g_deg[n0 + tid] : 0;
        if (tid < CHUNK) si[tid] = v;
        __syncthreads();
        if (tid == 0) {
            int s = 0;
            for (int i = 0; i < len; i++) s += si[i];
            g_part[blockIdx.x] = s;
        }
    }
    gridbar(gen0, 2);

    // ---- P1b: block 0 scans the 148 partials ----
    if (blockIdx.x == 0) {
        int pv = (tid < NB) ? g_part[tid] : 0;
        if (tid < NB) si[tid] = pv;
        __syncthreads();
        if (tid == 0) {
            int run = 0;
            for (int i = 0; i < NB; i++) { int t = si[i]; si[i] = run; run += t; }
        }
        __syncthreads();
        if (tid < NB) g_poff[tid] = si[tid];
    }
    gridbar(gen0, 3);

    // ---- P1c: per-chunk prefix -> rowstart/fill/dinv ----
    {
        int n0  = blockIdx.x * CHUNK;
        int len = NP - n0; if (len > CHUNK) len = CHUNK; if (len < 0) len = 0;
        int v = (tid < len) ? g_deg[n0 + tid] : 0;
        if (tid < CHUNK) si[tid] = v;
        __syncthreads();
        if (tid == 0) {
            int run = g_poff[blockIdx.x];
            for (int i = 0; i < len; i++) { int t = si[i]; si[i] = run; run += t; }
        }
        __syncthreads();
        if (tid < len) {
            int node = n0 + tid;
            int rs = si[tid];
            g_rowstart[node] = rs;
            g_fill[node]     = rs;
            g_dinv[node]     = rsqrtf((float)v + 1.0f);
        }
        if (blockIdx.x == 0 && tid == 0) g_rowstart[NP] = E_SG;
    }
    gridbar(gen0, 4);

    // ---- P2: CSR fill + prescaled x->bf16 + reset g_deg ----
    for (int e = gtid; e < E_SG; e += gs) {
        int d   = dst[e];
        int pos = atomicAdd(&g_fill[d], 1);
        g_csr_src[pos] = src[e];
    }
    {
        const float2* x2 = (const float2*)x;
        for (int i = gtid; i < NP * 128; i += gs) {
            int r = i >> 7;
            float di = g_dinv[r];
            float2 v = x2[i];
            g_xb[i] = pack2(v.x * di, v.y * di);
        }
    }
    for (int i = gtid; i < NP; i += gs) g_deg[i] = 0;
    gridbar(gen0, 5);

    // ---- P3: layer 1 ----
    layer_phase((const uint4*)g_xb, g_w1t, b1, nullptr,
                g_h1b, g_h1sb, true, 0, A_s, Ws, &s_tile);
    gridbar(gen0, 6);

    // ---- P4: layer 2 ----
    layer_phase((const uint4*)g_h1sb, g_w2t, b2, g_h1b,
                g_h2b, nullptr, false, 1, A_s, Ws, &s_tile);
    gridbar(gen0, 7);

    // ---- P5: scatter-mean pooling from bf16 h2 (pipelined + depth-3 tree) ----
    {
        const uint4* h2b = (const uint4*)g_h2b;
        float* P = (float*)smem_raw;
        for (int d = blockIdx.x; d < ND; d += NB) {
            int beg = g_drug_start[d];
            int end = g_drug_start[d + 1];
            float a[8] = {0.f, 0.f, 0.f, 0.f, 0.f, 0.f, 0.f, 0.f};
            int base = beg + wid * 32;
            int m    = min(32, end - base);
            int nidx = 0;
            if (base < end && lane < m) nidx = nodes[base + lane] * 32;
            while (base < end) {
                int nbase = base + NT;
                int nm    = min(32, end - nbase);
                int nnidx = 0;
                if (nbase < end && lane < nm)
                    nnidx = nodes[nbase + lane] * 32;   // prefetch next chunk
                int k = 0;
                for (; k + 8 <= m; k += 8) {
                    int i0 = __shfl_sync(0xffffffffu, nidx, k);
                    int i1 = __shfl_sync(0xffffffffu, nidx, k + 1);
                    int i2 = __shfl_sync(0xffffffffu, nidx, k + 2);
                    int i3 = __shfl_sync(0xffffffffu, nidx, k + 3);
                    int i4 = __shfl_sync(0xffffffffu, nidx, k + 4);
                    int i5 = __shfl_sync(0xffffffffu, nidx, k + 5);
                    int i6 = __shfl_sync(0xffffffffu, nidx, k + 6);
                    int i7 = __shfl_sync(0xffffffffu, nidx, k + 7);
                    uint4 u0 = h2b[i0 + lane];
                    uint4 u1 = h2b[i1 + lane];
                    uint4 u2 = h2b[i2 + lane];
                    uint4 u3 = h2b[i3 + lane];
                    uint4 u4 = h2b[i4 + lane];
                    uint4 u5 = h2b[i5 + lane];
                    uint4 u6 = h2b[i6 + lane];
                    uint4 u7 = h2b[i7 + lane];
                    uint4 t = pair_rows(
                        pair_rows(pair_rows(u0, u1), pair_rows(u2, u3)),
                        pair_rows(pair_rows(u4, u5), pair_rows(u6, u7)));
                    add_row(a, t);
                }
                for (; k + 4 <= m; k += 4) {
                    int i0 = __shfl_sync(0xffffffffu, nidx, k);
                    int i1 = __shfl_sync(0xffffffffu, nidx, k + 1);
                    int i2 = __shfl_sync(0xffffffffu, nidx, k + 2);
                    int i3 = __shfl_sync(0xffffffffu, nidx, k + 3);
                    uint4 u0 = h2b[i0 + lane];
                    uint4 u1 = h2b[i1 + lane];
                    uint4 u2 = h2b[i2 + lane];
                    uint4 u3 = h2b[i3 + lane];
                    uint4 t = pair_rows(pair_rows(u0, u1), pair_rows(u2, u3));
                    add_row(a, t);
                }
                for (; k < m; k++) {
                    int i0 = __shfl_sync(0xffffffffu, nidx, k);
                    uint4 u0 = h2b[i0 + lane];
                    add_row(a, u0);
                }
                base = nbase; m = nm; nidx = nnidx;
            }
            __syncthreads();
            *(float4*)&P[wid * 256 + lane * 8]     = make_float4(a[0], a[1], a[2], a[3]);
            *(float4*)&P[wid * 256 + lane * 8 + 4] = make_float4(a[4], a[5], a[6], a[7]);
            __syncthreads();
            if (tid < 256) {
                float s = 0.f;
                #pragma unroll
                for (int w = 0; w < NWARP; w++) s += P[w * 256 + tid];
                float inv = 1.0f / fmaxf((float)(end - beg), 1.0f);
                g_drug[d * 256 + tid] = s * inv;
            }
            __syncthreads();
        }
    }
    gridbar(gen0, 8);

    // ---- P6: prediction head ----
    {
        const float4* gd = (const float4*)g_drug;
        for (int p = blockIdx.x * NWARP + wid; p < B_DD; p += NB * NWARP) {
            int a = ddb[p];
            int b = ddb[B_DD + p];
            float4 va0 = gd[a * 64 + lane], va1 = gd[a * 64 + 32 + lane];
            float4 vb0 = gd[b * 64 + lane], vb1 = gd[b * 64 + 32 + lane];
            float s = va0.x * vb0.x + va0.y * vb0.y + va0.z * vb0.z + va0.w * vb0.w
                    + va1.x * vb1.x + va1.y * vb1.y + va1.z * vb1.z + va1.w * vb1.w;
            #pragma unroll
            for (int off = 16; off; off >>= 1)
                s += __shfl_down_sync(0xffffffffu, s, off);
            if (lane == 0) out[p] = s;
        }
    }
}

// ---------------- launch ----------------------------------------------------
extern "C" void kernel_launch(void* const* d_in, const int* in_sizes, int n_in,
                              void* d_out, int out_size) {
    const float* x     = (const float*)d_in[0];
    const int*   ddb   = (const int*)d_in[1];
    const int*   sg_ei = (const int*)d_in[4];
    const int*   nodes = (const int*)d_in[5];
    const int*   avgix = (const int*)d_in[6];
    const float* W1    = (const float*)d_in[7];
    const float* b1    = (const float*)d_in[8];
    const float* W2    = (const float*)d_in[9];
    const float* b2    = (const float*)d_in[10];
    float* out = (float*)d_out;

    const int smem_bytes = 33792 + 135168;   // 168960
    static bool attr_set = false;
    if (!attr_set) {
        cudaFuncSetAttribute(mega_kernel, cudaFuncAttributeMaxDynamicSharedMemorySize,
                             smem_bytes);
        attr_set = true;
    }

    mega_kernel<<<NB, NT, smem_bytes>>>(x, ddb, sg_ei, sg_ei + E_SG,
                                        nodes, avgix, W1, b1, W2, b2, out);
}